// round 5
// baseline (speedup 1.0000x reference)
#include <cuda_runtime.h>
#include <math.h>

// Problem constants
constexpr int S_    = 81;    // sequence length
constexpr int D_    = 64;    // head dim
constexpr int QSTR_ = 68;    // padded row stride (floats): conflict-free float4 LDS across rows
constexpr int PSTR_ = 81;    // probs row stride (row-contiguous / broadcast access only)
constexpr int NT_   = 256;
constexpr int NW_   = 8;
constexpr int NTILE_= 21;    // ceil(81/4)

constexpr int SZ_Q   = S_ * QSTR_;   // 5508
constexpr int SZ_K   = S_ * QSTR_;   // 5508
constexpr int SZ_EV  = S_ * QSTR_;   // 5508 : causal E slice (rows 80..160) / later V
constexpr int SZ_P   = S_ * PSTR_;   // 6561
constexpr int SZ_SCR = NW_ * 4 * S_; // 2592 : per-warp M scratch (4 rows x 81 t-values)
constexpr int SMEM_FLOATS = SZ_Q + SZ_K + SZ_EV + SZ_P + SZ_SCR; // 25677 -> 102708 B (2 CTAs/SM)

__global__ __launch_bounds__(NT_, 1)
void rpsa_kernel(const float* __restrict__ Qg_, const float* __restrict__ Kg_,
                 const float* __restrict__ Vg_, const float* __restrict__ Eg,
                 const int* __restrict__ causal_p, float* __restrict__ outg_)
{
    extern __shared__ float sm[];
    float* sQ  = sm;
    float* sK  = sQ + SZ_Q;
    float* sEV = sK + SZ_K;              // causal E slice; V afterwards
    float* sP  = sEV + SZ_EV;
    float* sScr= sP + SZ_P;

    const int bh   = blockIdx.x;
    const int tid  = threadIdx.x;
    const int warp = tid >> 5;
    const int lane = tid & 31;
    const int causal = *causal_p;
    const float scale = 0.03608439182435161f;  // 1/sqrt(768)

    const float* Qg = Qg_ + (size_t)bh * (S_ * D_);
    const float* Kg = Kg_ + (size_t)bh * (S_ * D_);
    const float* Vg = Vg_ + (size_t)bh * (S_ * D_);
    float*     outg = outg_ + (size_t)bh * (S_ * D_);

    // ---------------- Stage A: load Q, K, E-slice (float4, coalesced) ----------------
    #pragma unroll 1
    for (int t = tid; t < (S_ * D_) / 4; t += NT_) {
        int e = t << 2, r = e >> 6, c = e & 63;
        *(float4*)&sQ[r * QSTR_ + c] = *(const float4*)&Qg[e];
        *(float4*)&sK[r * QSTR_ + c] = *(const float4*)&Kg[e];
        if (causal) {
            // local E row t holds emb_table[80 + t]  (only rels >= 80 used when causal)
            *(float4*)&sEV[r * QSTR_ + c] = *(const float4*)&Eg[(S_ - 1) * D_ + e];
        }
    }
    __syncthreads();

    // ---------------- Stage C: logits -> sP ------------------------------------------
    if (causal) {
        // Per tile: compute both  acc_K[r][g] = Q[i] . K[j]    (j = lane+32g)
        //                   and   acc_M[r][g] = Q[i] . E80[t]  (t = lane+32g)
        // then gather bias = acc_M[r][i-j] via warp-local smem scratch.
        float* scr = sScr + warp * (4 * S_);
        for (int tile = warp; tile < NTILE_; tile += NW_) {
            const int i0   = tile * 4;
            const int imax = min(i0 + 3, S_ - 1);
            const int ng   = (imax >> 5) + 1;     // groups covering both j<=imax and t<=imax

            float accK[4][3], accM[4][3];
            #pragma unroll
            for (int r = 0; r < 4; r++)
                #pragma unroll
                for (int g = 0; g < 3; g++) { accK[r][g] = 0.f; accM[r][g] = 0.f; }

            int ival[4], ri[4];
            #pragma unroll
            for (int r = 0; r < 4; r++) { ival[r] = min(i0 + r, S_ - 1); ri[r] = ival[r] * QSTR_; }
            int rowg[3];
            #pragma unroll
            for (int g = 0; g < 3; g++) rowg[g] = min(lane + 32 * g, S_ - 1) * QSTR_;

            for (int d = 0; d < D_; d += 4) {
                float4 q[4];
                #pragma unroll
                for (int r = 0; r < 4; r++) q[r] = *(const float4*)&sQ[ri[r] + d];
                #pragma unroll
                for (int g = 0; g < 3; g++) {
                    if (g < ng) {
                        float4 k4 = *(const float4*)&sK [rowg[g] + d];
                        float4 e4 = *(const float4*)&sEV[rowg[g] + d];
                        #pragma unroll
                        for (int r = 0; r < 4; r++) {
                            float a = accK[r][g];
                            a = fmaf(q[r].x, k4.x, a); a = fmaf(q[r].y, k4.y, a);
                            a = fmaf(q[r].z, k4.z, a); a = fmaf(q[r].w, k4.w, a);
                            accK[r][g] = a;
                            float b = accM[r][g];
                            b = fmaf(q[r].x, e4.x, b); b = fmaf(q[r].y, e4.y, b);
                            b = fmaf(q[r].z, e4.z, b); b = fmaf(q[r].w, e4.w, b);
                            accM[r][g] = b;
                        }
                    }
                }
            }

            // write M values to warp scratch: scr[r][t] = Q[i_r] . E[80+t]
            #pragma unroll
            for (int r = 0; r < 4; r++) {
                #pragma unroll
                for (int g = 0; g < 3; g++) {
                    int t = lane + 32 * g;
                    if (g < ng && t < S_) scr[r * S_ + t] = accM[r][g];
                }
            }
            __syncwarp();

            #pragma unroll
            for (int r = 0; r < 4; r++) {
                int i = i0 + r;
                if (i < S_) {
                    #pragma unroll
                    for (int g = 0; g < 3; g++) {
                        int j = lane + 32 * g;
                        if (j < S_) {
                            float v;
                            if (j > i) v = -1.0e9f;
                            else       v = (accK[r][g] + scr[r * S_ + (i - j)]) * scale;
                            sP[i * PSTR_ + j] = v;
                        }
                    }
                }
            }
            __syncwarp();   // cross-lane WAR: all reads of scratch done before next tile overwrites
        }
    } else {
        // Non-causal fallback: fused QK + bias with E read from global (L2-resident, 41 KB).
        for (int tile = warp; tile < NTILE_; tile += NW_) {
            const int i0 = tile * 4;
            float acc[4][3];
            #pragma unroll
            for (int r = 0; r < 4; r++) { acc[r][0] = acc[r][1] = acc[r][2] = 0.f; }
            int ival[4], ri[4];
            #pragma unroll
            for (int r = 0; r < 4; r++) { ival[r] = min(i0 + r, S_ - 1); ri[r] = ival[r] * QSTR_; }
            int jval[3], ki[3];
            #pragma unroll
            for (int g = 0; g < 3; g++) { jval[g] = min(lane + 32 * g, S_ - 1); ki[g] = jval[g] * QSTR_; }

            for (int d = 0; d < D_; d += 4) {
                float4 q[4];
                #pragma unroll
                for (int r = 0; r < 4; r++) q[r] = *(const float4*)&sQ[ri[r] + d];
                #pragma unroll
                for (int g = 0; g < 3; g++) {
                    float4 k4 = *(const float4*)&sK[ki[g] + d];
                    #pragma unroll
                    for (int r = 0; r < 4; r++) {
                        const float4* ep = (const float4*)&Eg[(size_t)(S_ - 1 + ival[r] - jval[g]) * D_ + d];
                        float4 e4 = *ep;
                        float a = acc[r][g];
                        a = fmaf(q[r].x, k4.x, a); a = fmaf(q[r].x, e4.x, a);
                        a = fmaf(q[r].y, k4.y, a); a = fmaf(q[r].y, e4.y, a);
                        a = fmaf(q[r].z, k4.z, a); a = fmaf(q[r].z, e4.z, a);
                        a = fmaf(q[r].w, k4.w, a); a = fmaf(q[r].w, e4.w, a);
                        acc[r][g] = a;
                    }
                }
            }
            #pragma unroll
            for (int r = 0; r < 4; r++) {
                int i = i0 + r;
                if (i < S_) {
                    #pragma unroll
                    for (int g = 0; g < 3; g++) {
                        int j = lane + 32 * g;
                        if (j < S_) sP[i * PSTR_ + j] = acc[r][g] * scale;
                    }
                }
            }
        }
    }
    __syncthreads();   // sP complete; E reads done -> safe to overwrite with V

    // ---------------- V load (overwrites E region) -----------------------------------
    #pragma unroll 1
    for (int t = tid; t < (S_ * D_) / 4; t += NT_) {
        int e = t << 2, r = e >> 6, c = e & 63;
        *(float4*)&sEV[r * QSTR_ + c] = *(const float4*)&Vg[e];
    }

    // ---------------- Softmax (one warp per row) -------------------------------------
    for (int i = warp; i < S_; i += NW_) {
        float* row = &sP[i * PSTR_];
        float a = row[lane];
        float b = row[lane + 32];
        float c = (lane < S_ - 64) ? row[lane + 64] : -3.0e38f;
        float m = fmaxf(a, fmaxf(b, c));
        #pragma unroll
        for (int o = 16; o > 0; o >>= 1) m = fmaxf(m, __shfl_xor_sync(0xffffffffu, m, o));
        float e0 = expf(a - m), e1 = expf(b - m);
        float e2 = (lane < S_ - 64) ? expf(c - m) : 0.f;
        float s = e0 + e1 + e2;
        #pragma unroll
        for (int o = 16; o > 0; o >>= 1) s += __shfl_xor_sync(0xffffffffu, s, o);
        float inv = 1.0f / s;
        row[lane]      = e0 * inv;
        row[lane + 32] = e1 * inv;
        if (lane < S_ - 64) row[lane + 64] = e2 * inv;
    }
    __syncthreads();

    // ---------------- Stage E: PV  out[i][d] = sum_j P[i][j] * V[j][d] ---------------
    for (int tile = warp; tile < NTILE_; tile += NW_) {
        const int i0   = tile * 4;
        const int imax = min(i0 + 3, S_ - 1);
        const int jmax = causal ? imax : (S_ - 1);   // masked P entries are exactly 0
        float2 acc[4];
        #pragma unroll
        for (int r = 0; r < 4; r++) { acc[r].x = 0.f; acc[r].y = 0.f; }
        int ri[4];
        #pragma unroll
        for (int r = 0; r < 4; r++) ri[r] = min(i0 + r, S_ - 1) * PSTR_;
        const int dcol = 2 * lane;

        #pragma unroll 2
        for (int j = 0; j <= jmax; j++) {
            float2 v = *(const float2*)&sEV[j * QSTR_ + dcol];
            #pragma unroll
            for (int r = 0; r < 4; r++) {
                float p = sP[ri[r] + j];
                acc[r].x = fmaf(p, v.x, acc[r].x);
                acc[r].y = fmaf(p, v.y, acc[r].y);
            }
        }
        #pragma unroll
        for (int r = 0; r < 4; r++) {
            int i = i0 + r;
            if (i < S_) *(float2*)&outg[i * D_ + dcol] = acc[r];
        }
    }
}

extern "C" void kernel_launch(void* const* d_in, const int* in_sizes, int n_in,
                              void* d_out, int out_size)
{
    const float* Q  = (const float*)d_in[0];
    const float* K  = (const float*)d_in[1];
    const float* V  = (const float*)d_in[2];
    const float* E  = (const float*)d_in[3];
    const int*   uc = (const int*)d_in[4];
    float* out = (float*)d_out;

    const int nbh = out_size / (S_ * D_);   // 4096 for the bench shape
    const size_t smem = (size_t)SMEM_FLOATS * sizeof(float);  // 102708 B -> 2 CTAs/SM

    cudaFuncSetAttribute(rpsa_kernel, cudaFuncAttributeMaxDynamicSharedMemorySize, (int)smem);
    rpsa_kernel<<<nbh, NT_, smem>>>(Q, K, V, E, uc, out);
}

// round 7
// speedup vs baseline: 1.4243x; 1.4243x over previous
#include <cuda_runtime.h>
#include <math.h>

// Problem constants
constexpr int S_    = 81;    // sequence length
constexpr int D_    = 64;    // head dim
constexpr int QSTR_ = 68;    // padded row stride (floats): conflict-free float4 LDS across rows
constexpr int PSTR_ = 81;    // probs row stride (row-contiguous / broadcast access only)
constexpr int NT_   = 256;
constexpr int NW_   = 8;
constexpr int NTILE_= 21;    // ceil(81/4)

constexpr int SZ_Q   = S_ * QSTR_;   // 5508
constexpr int SZ_K   = S_ * QSTR_;   // 5508
constexpr int SZ_EV  = S_ * QSTR_;   // 5508 : causal E slice (rows 80..160) / later V
constexpr int SZ_P   = S_ * PSTR_;   // 6561
constexpr int SZ_SCR = NW_ * 4 * S_; // 2592 : per-warp M scratch (4 rows x 81 t-values)
constexpr int SMEM_FLOATS = SZ_Q + SZ_K + SZ_EV + SZ_P + SZ_SCR; // 25677 -> 102708 B (2 CTAs/SM)

__global__ __launch_bounds__(NT_, 2)   // 2 CTAs/SM: regs <=128 AND smem 102.7KB both fit
void rpsa_kernel(const float* __restrict__ Qg_, const float* __restrict__ Kg_,
                 const float* __restrict__ Vg_, const float* __restrict__ Eg,
                 const int* __restrict__ causal_p, float* __restrict__ outg_)
{
    extern __shared__ float sm[];
    float* sQ  = sm;
    float* sK  = sQ + SZ_Q;
    float* sEV = sK + SZ_K;              // causal E slice; V afterwards
    float* sP  = sEV + SZ_EV;
    float* sScr= sP + SZ_P;

    const int bh   = blockIdx.x;
    const int tid  = threadIdx.x;
    const int warp = tid >> 5;
    const int lane = tid & 31;
    const int causal = *causal_p;
    const float scale = 0.03608439182435161f;  // 1/sqrt(768)

    const float* Qg = Qg_ + (size_t)bh * (S_ * D_);
    const float* Kg = Kg_ + (size_t)bh * (S_ * D_);
    const float* Vg = Vg_ + (size_t)bh * (S_ * D_);
    float*     outg = outg_ + (size_t)bh * (S_ * D_);

    // ---------------- Stage A: load Q, K, E-slice (float4, coalesced) ----------------
    #pragma unroll 1
    for (int t = tid; t < (S_ * D_) / 4; t += NT_) {
        int e = t << 2, r = e >> 6, c = e & 63;
        *(float4*)&sQ[r * QSTR_ + c] = *(const float4*)&Qg[e];
        *(float4*)&sK[r * QSTR_ + c] = *(const float4*)&Kg[e];
        if (causal) {
            // local E row t holds emb_table[80 + t]  (only rels >= 80 used when causal)
            *(float4*)&sEV[r * QSTR_ + c] = *(const float4*)&Eg[(S_ - 1) * D_ + e];
        }
    }
    __syncthreads();

    // ---------------- Stage C: logits -> sP ------------------------------------------
    if (causal) {
        // Two low-pressure passes per tile:
        //   K-pass: accK[r][g] = Q[i_r] . K[j]     (j = lane+32g)
        //   M-pass: accM[r][g] = Q[i_r] . E80[t]   (t = lane+32g)  -> warp scratch
        // then logits[i][j] = (accK + scr[r][i-j]) * scale with causal mask.
        float* scr = sScr + warp * (4 * S_);
        for (int tile = warp; tile < NTILE_; tile += NW_) {
            const int i0   = tile * 4;
            const int imax = min(i0 + 3, S_ - 1);
            const int ng   = (imax >> 5) + 1;     // groups covering both j<=imax and t<=imax

            int ri[4];
            #pragma unroll
            for (int r = 0; r < 4; r++) ri[r] = min(i0 + r, S_ - 1) * QSTR_;
            int rowg[3];
            #pragma unroll
            for (int g = 0; g < 3; g++) rowg[g] = min(lane + 32 * g, S_ - 1) * QSTR_;

            // ---- K pass ----
            float accK[4][3];
            #pragma unroll
            for (int r = 0; r < 4; r++) { accK[r][0] = accK[r][1] = accK[r][2] = 0.f; }
            for (int d = 0; d < D_; d += 4) {
                float4 q[4];
                #pragma unroll
                for (int r = 0; r < 4; r++) q[r] = *(const float4*)&sQ[ri[r] + d];
                #pragma unroll
                for (int g = 0; g < 3; g++) {
                    if (g < ng) {
                        float4 k4 = *(const float4*)&sK[rowg[g] + d];
                        #pragma unroll
                        for (int r = 0; r < 4; r++) {
                            float a = accK[r][g];
                            a = fmaf(q[r].x, k4.x, a); a = fmaf(q[r].y, k4.y, a);
                            a = fmaf(q[r].z, k4.z, a); a = fmaf(q[r].w, k4.w, a);
                            accK[r][g] = a;
                        }
                    }
                }
            }

            // ---- M pass ----
            float accM[4][3];
            #pragma unroll
            for (int r = 0; r < 4; r++) { accM[r][0] = accM[r][1] = accM[r][2] = 0.f; }
            for (int d = 0; d < D_; d += 4) {
                float4 q[4];
                #pragma unroll
                for (int r = 0; r < 4; r++) q[r] = *(const float4*)&sQ[ri[r] + d];
                #pragma unroll
                for (int g = 0; g < 3; g++) {
                    if (g < ng) {
                        float4 e4 = *(const float4*)&sEV[rowg[g] + d];
                        #pragma unroll
                        for (int r = 0; r < 4; r++) {
                            float b = accM[r][g];
                            b = fmaf(q[r].x, e4.x, b); b = fmaf(q[r].y, e4.y, b);
                            b = fmaf(q[r].z, e4.z, b); b = fmaf(q[r].w, e4.w, b);
                            accM[r][g] = b;
                        }
                    }
                }
            }

            // write M values to warp scratch: scr[r][t] = Q[i_r] . E[80+t]
            #pragma unroll
            for (int r = 0; r < 4; r++) {
                #pragma unroll
                for (int g = 0; g < 3; g++) {
                    int t = lane + 32 * g;
                    if (g < ng && t < S_) scr[r * S_ + t] = accM[r][g];
                }
            }
            __syncwarp();

            #pragma unroll
            for (int r = 0; r < 4; r++) {
                int i = i0 + r;
                if (i < S_) {
                    #pragma unroll
                    for (int g = 0; g < 3; g++) {
                        int j = lane + 32 * g;
                        if (j < S_) {
                            float v;
                            if (j > i) v = -1.0e9f;
                            else       v = (accK[r][g] + scr[r * S_ + (i - j)]) * scale;
                            sP[i * PSTR_ + j] = v;
                        }
                    }
                }
            }
            __syncwarp();   // cross-lane WAR: all reads of scratch done before next tile overwrites
        }
    } else {
        // Non-causal fallback: fused QK + bias with E read from global (L2-resident, 41 KB).
        for (int tile = warp; tile < NTILE_; tile += NW_) {
            const int i0 = tile * 4;
            float acc[4][3];
            #pragma unroll
            for (int r = 0; r < 4; r++) { acc[r][0] = acc[r][1] = acc[r][2] = 0.f; }
            int ival[4], ri[4];
            #pragma unroll
            for (int r = 0; r < 4; r++) { ival[r] = min(i0 + r, S_ - 1); ri[r] = ival[r] * QSTR_; }
            int jval[3], ki[3];
            #pragma unroll
            for (int g = 0; g < 3; g++) { jval[g] = min(lane + 32 * g, S_ - 1); ki[g] = jval[g] * QSTR_; }

            for (int d = 0; d < D_; d += 4) {
                float4 q[4];
                #pragma unroll
                for (int r = 0; r < 4; r++) q[r] = *(const float4*)&sQ[ri[r] + d];
                #pragma unroll
                for (int g = 0; g < 3; g++) {
                    float4 k4 = *(const float4*)&sK[ki[g] + d];
                    #pragma unroll
                    for (int r = 0; r < 4; r++) {
                        const float4* ep = (const float4*)&Eg[(size_t)(S_ - 1 + ival[r] - jval[g]) * D_ + d];
                        float4 e4 = *ep;
                        float a = acc[r][g];
                        a = fmaf(q[r].x, k4.x, a); a = fmaf(q[r].x, e4.x, a);
                        a = fmaf(q[r].y, k4.y, a); a = fmaf(q[r].y, e4.y, a);
                        a = fmaf(q[r].z, k4.z, a); a = fmaf(q[r].z, e4.z, a);
                        a = fmaf(q[r].w, k4.w, a); a = fmaf(q[r].w, e4.w, a);
                        acc[r][g] = a;
                    }
                }
            }
            #pragma unroll
            for (int r = 0; r < 4; r++) {
                int i = i0 + r;
                if (i < S_) {
                    #pragma unroll
                    for (int g = 0; g < 3; g++) {
                        int j = lane + 32 * g;
                        if (j < S_) sP[i * PSTR_ + j] = acc[r][g] * scale;
                    }
                }
            }
        }
    }
    __syncthreads();   // sP complete; E reads done -> safe to overwrite with V

    // ---------------- V load (overwrites E region) -----------------------------------
    #pragma unroll 1
    for (int t = tid; t < (S_ * D_) / 4; t += NT_) {
        int e = t << 2, r = e >> 6, c = e & 63;
        *(float4*)&sEV[r * QSTR_ + c] = *(const float4*)&Vg[e];
    }

    // ---------------- Softmax (one warp per row) -------------------------------------
    for (int i = warp; i < S_; i += NW_) {
        float* row = &sP[i * PSTR_];
        float a = row[lane];
        float b = row[lane + 32];
        float c = (lane < S_ - 64) ? row[lane + 64] : -3.0e38f;
        float m = fmaxf(a, fmaxf(b, c));
        #pragma unroll
        for (int o = 16; o > 0; o >>= 1) m = fmaxf(m, __shfl_xor_sync(0xffffffffu, m, o));
        float e0 = expf(a - m), e1 = expf(b - m);
        float e2 = (lane < S_ - 64) ? expf(c - m) : 0.f;
        float s = e0 + e1 + e2;
        #pragma unroll
        for (int o = 16; o > 0; o >>= 1) s += __shfl_xor_sync(0xffffffffu, s, o);
        float inv = 1.0f / s;
        row[lane]      = e0 * inv;
        row[lane + 32] = e1 * inv;
        if (lane < S_ - 64) row[lane + 64] = e2 * inv;
    }
    __syncthreads();

    // ---------------- Stage E: PV  out[i][d] = sum_j P[i][j] * V[j][d] ---------------
    for (int tile = warp; tile < NTILE_; tile += NW_) {
        const int i0   = tile * 4;
        const int imax = min(i0 + 3, S_ - 1);
        const int jmax = causal ? imax : (S_ - 1);   // masked P entries are exactly 0
        float2 acc[4];
        #pragma unroll
        for (int r = 0; r < 4; r++) { acc[r].x = 0.f; acc[r].y = 0.f; }
        int ri[4];
        #pragma unroll
        for (int r = 0; r < 4; r++) ri[r] = min(i0 + r, S_ - 1) * PSTR_;
        const int dcol = 2 * lane;

        #pragma unroll 2
        for (int j = 0; j <= jmax; j++) {
            float2 v = *(const float2*)&sEV[j * QSTR_ + dcol];
            #pragma unroll
            for (int r = 0; r < 4; r++) {
                float p = sP[ri[r] + j];
                acc[r].x = fmaf(p, v.x, acc[r].x);
                acc[r].y = fmaf(p, v.y, acc[r].y);
            }
        }
        #pragma unroll
        for (int r = 0; r < 4; r++) {
            int i = i0 + r;
            if (i < S_) *(float2*)&outg[i * D_ + dcol] = acc[r];
        }
    }
}

extern "C" void kernel_launch(void* const* d_in, const int* in_sizes, int n_in,
                              void* d_out, int out_size)
{
    const float* Q  = (const float*)d_in[0];
    const float* K  = (const float*)d_in[1];
    const float* V  = (const float*)d_in[2];
    const float* E  = (const float*)d_in[3];
    const int*   uc = (const int*)d_in[4];
    float* out = (float*)d_out;

    const int nbh = out_size / (S_ * D_);   // 4096 for the bench shape
    const size_t smem = (size_t)SMEM_FLOATS * sizeof(float);  // 102708 B -> 2 CTAs/SM

    cudaFuncSetAttribute(rpsa_kernel, cudaFuncAttributeMaxDynamicSharedMemorySize, (int)smem);
    rpsa_kernel<<<nbh, NT_, smem>>>(Q, K, V, E, uc, out);
}

// round 9
// speedup vs baseline: 1.5823x; 1.1109x over previous
#include <cuda_runtime.h>
#include <math.h>

// Problem constants
constexpr int S_    = 81;    // sequence length
constexpr int D_    = 64;    // head dim
constexpr int KSTR_ = 68;    // K/E row stride: 68 mod 8 == 4 -> conflict-free float4 row-distinct LDS
constexpr int VSTR_ = 64;    // Q/V row stride: reads are broadcast (Q) or lane-consecutive (V)
constexpr int NT_   = 512;
constexpr int NW_   = 16;
constexpr int NR_   = 2;     // query rows per tile
constexpr int NTILE_= 41;    // ceil(81/2)

constexpr int SZ_Q   = S_ * VSTR_;        // 5184
constexpr int SZ_K   = S_ * KSTR_;        // 5508
constexpr int SZ_E   = S_ * KSTR_;        // 5508 (causal slice: emb rows 80..160)
constexpr int SZ_V   = S_ * VSTR_;        // 5184
constexpr int SZ_SCR = NW_ * NR_ * S_;    // 2592 (per-warp scratch: bias M values, then probs)
constexpr int SMEM_FLOATS = SZ_Q + SZ_K + SZ_E + SZ_V + SZ_SCR; // 23976 -> 95904 B (2 CTAs/SM)

__global__ __launch_bounds__(NT_, 2)   // 2 CTAs x 512 thr -> regs capped at 64, 32 warps/SM
void rpsa_kernel(const float* __restrict__ Qg_, const float* __restrict__ Kg_,
                 const float* __restrict__ Vg_, const float* __restrict__ Eg,
                 const int* __restrict__ causal_p, float* __restrict__ outg_)
{
    extern __shared__ float sm[];
    float* sQ  = sm;
    float* sK  = sQ + SZ_Q;
    float* sE  = sK + SZ_K;
    float* sV  = sE + SZ_E;
    float* sScr= sV + SZ_V;

    const int bh   = blockIdx.x;
    const int tid  = threadIdx.x;
    const int warp = tid >> 5;
    const int lane = tid & 31;
    const int causal = *causal_p;
    const float scale = 0.03608439182435161f;  // 1/sqrt(768)

    const float* Qg = Qg_ + (size_t)bh * (S_ * D_);
    const float* Kg = Kg_ + (size_t)bh * (S_ * D_);
    const float* Vg = Vg_ + (size_t)bh * (S_ * D_);
    float*     outg = outg_ + (size_t)bh * (S_ * D_);

    // ------------- Stage A: load Q, K, V, E-slice (float4, coalesced), ONE barrier ----
    #pragma unroll 1
    for (int t = tid; t < (S_ * D_) / 4; t += NT_) {
        int e = t << 2, r = e >> 6, c = e & 63;
        *(float4*)&sQ[r * VSTR_ + c] = *(const float4*)&Qg[e];
        *(float4*)&sK[r * KSTR_ + c] = *(const float4*)&Kg[e];
        *(float4*)&sV[r * VSTR_ + c] = *(const float4*)&Vg[e];
        // local E row t holds emb_table[80 + t] (rels >= 80; only ones used when causal)
        *(float4*)&sE[r * KSTR_ + c] = *(const float4*)&Eg[(S_ - 1) * D_ + e];
    }
    __syncthreads();

    // ------------- Warp-autonomous: logits -> softmax -> PV per 2-row tile ------------
    float* scr = sScr + warp * (NR_ * S_);
    const int dcol = 2 * lane;

    for (int tile = warp; tile < NTILE_; tile += NW_) {
        const int i0   = tile * NR_;
        const int imax = min(i0 + NR_ - 1, S_ - 1);
        const int ng   = causal ? ((imax >> 5) + 1) : 3;

        int iv0 = min(i0, S_ - 1), iv1 = imax;          // clamped row indices
        const int ri0 = iv0 * VSTR_, ri1 = iv1 * VSTR_;
        int rowg[3];
        #pragma unroll
        for (int g = 0; g < 3; g++) rowg[g] = min(lane + 32 * g, S_ - 1) * KSTR_;

        // ---- K pass: accK[r][g] = Q[i_r] . K[j],  j = lane+32g ----
        float accK[NR_][3];
        #pragma unroll
        for (int r = 0; r < NR_; r++) { accK[r][0] = accK[r][1] = accK[r][2] = 0.f; }
        for (int d = 0; d < D_; d += 4) {
            float4 q0 = *(const float4*)&sQ[ri0 + d];
            float4 q1 = *(const float4*)&sQ[ri1 + d];
            #pragma unroll
            for (int g = 0; g < 3; g++) {
                if (g < ng) {
                    float4 k4 = *(const float4*)&sK[rowg[g] + d];
                    float a0 = accK[0][g], a1 = accK[1][g];
                    a0 = fmaf(q0.x, k4.x, a0); a1 = fmaf(q1.x, k4.x, a1);
                    a0 = fmaf(q0.y, k4.y, a0); a1 = fmaf(q1.y, k4.y, a1);
                    a0 = fmaf(q0.z, k4.z, a0); a1 = fmaf(q1.z, k4.z, a1);
                    a0 = fmaf(q0.w, k4.w, a0); a1 = fmaf(q1.w, k4.w, a1);
                    accK[0][g] = a0; accK[1][g] = a1;
                }
            }
        }

        if (causal) {
            // ---- M pass: accM[r][g] = Q[i_r] . E80[t],  t = lane+32g -> scratch ----
            float accM[NR_][3];
            #pragma unroll
            for (int r = 0; r < NR_; r++) { accM[r][0] = accM[r][1] = accM[r][2] = 0.f; }
            for (int d = 0; d < D_; d += 4) {
                float4 q0 = *(const float4*)&sQ[ri0 + d];
                float4 q1 = *(const float4*)&sQ[ri1 + d];
                #pragma unroll
                for (int g = 0; g < 3; g++) {
                    if (g < ng) {
                        float4 e4 = *(const float4*)&sE[rowg[g] + d];
                        float b0 = accM[0][g], b1 = accM[1][g];
                        b0 = fmaf(q0.x, e4.x, b0); b1 = fmaf(q1.x, e4.x, b1);
                        b0 = fmaf(q0.y, e4.y, b0); b1 = fmaf(q1.y, e4.y, b1);
                        b0 = fmaf(q0.z, e4.z, b0); b1 = fmaf(q1.z, e4.z, b1);
                        b0 = fmaf(q0.w, e4.w, b0); b1 = fmaf(q1.w, e4.w, b1);
                        accM[0][g] = b0; accM[1][g] = b1;
                    }
                }
            }
            #pragma unroll
            for (int r = 0; r < NR_; r++) {
                #pragma unroll
                for (int g = 0; g < 3; g++) {
                    int t = lane + 32 * g;
                    if (g < ng && t < S_) scr[r * S_ + t] = accM[r][g];
                }
            }
            __syncwarp();
            // bias gather + mask into accK (becomes logits)
            #pragma unroll
            for (int r = 0; r < NR_; r++) {
                int i = (r == 0) ? iv0 : iv1;
                #pragma unroll
                for (int g = 0; g < 3; g++) {
                    int j = lane + 32 * g;
                    if (g < ng && j <= i)
                        accK[r][g] = (accK[r][g] + scr[r * S_ + (i - j)]) * scale;
                    else
                        accK[r][g] = -3.0e38f;
                }
            }
            __syncwarp();   // bias reads done before scratch is overwritten with probs
        } else {
            // non-causal: add bias from global E (L2-resident), no mask
            #pragma unroll
            for (int r = 0; r < NR_; r++) {
                int i = (r == 0) ? iv0 : iv1;
                #pragma unroll
                for (int g = 0; g < 3; g++) {
                    int j = lane + 32 * g;
                    if (j < S_) {
                        float bias = 0.f;
                        const float* erow = &Eg[(size_t)(S_ - 1 + i - j) * D_];
                        const float* qrow = &sQ[(r == 0) ? ri0 : ri1];
                        for (int d = 0; d < D_; d += 4) {
                            float4 e4 = *(const float4*)&erow[d];
                            float4 q4 = *(const float4*)&qrow[d];
                            bias = fmaf(q4.x, e4.x, bias); bias = fmaf(q4.y, e4.y, bias);
                            bias = fmaf(q4.z, e4.z, bias); bias = fmaf(q4.w, e4.w, bias);
                        }
                        accK[r][g] = (accK[r][g] + bias) * scale;
                    } else {
                        accK[r][g] = -3.0e38f;
                    }
                }
            }
        }

        // ---- register softmax per row (lanes hold j = lane, lane+32, lane+64) ----
        #pragma unroll
        for (int r = 0; r < NR_; r++) {
            float m = fmaxf(accK[r][0], fmaxf(accK[r][1], accK[r][2]));
            #pragma unroll
            for (int o = 16; o > 0; o >>= 1) m = fmaxf(m, __shfl_xor_sync(0xffffffffu, m, o));
            float e0 = expf(accK[r][0] - m);
            float e1 = expf(accK[r][1] - m);
            float e2 = expf(accK[r][2] - m);
            float s = e0 + e1 + e2;
            #pragma unroll
            for (int o = 16; o > 0; o >>= 1) s += __shfl_xor_sync(0xffffffffu, s, o);
            float inv = 1.0f / s;
            accK[r][0] = e0 * inv; accK[r][1] = e1 * inv; accK[r][2] = e2 * inv;
        }
        // probs -> scratch (masked entries are exactly 0)
        #pragma unroll
        for (int r = 0; r < NR_; r++) {
            #pragma unroll
            for (int g = 0; g < 3; g++) {
                int j = lane + 32 * g;
                if (j < S_) scr[r * S_ + j] = accK[r][g];
            }
        }
        __syncwarp();

        // ---- PV: out[i][d] = sum_j P[i][j] * V[j][d]  (d = dcol, dcol+1) ----
        const int jmax = causal ? imax : (S_ - 1);
        float2 a0 = {0.f, 0.f}, a1 = {0.f, 0.f};
        #pragma unroll 3
        for (int j = 0; j <= jmax; j++) {
            float2 v = *(const float2*)&sV[j * VSTR_ + dcol];
            float p0 = scr[j], p1 = scr[S_ + j];
            a0.x = fmaf(p0, v.x, a0.x); a0.y = fmaf(p0, v.y, a0.y);
            a1.x = fmaf(p1, v.x, a1.x); a1.y = fmaf(p1, v.y, a1.y);
        }
        if (i0 < S_)     *(float2*)&outg[i0 * D_ + dcol]       = a0;
        if (i0 + 1 < S_) *(float2*)&outg[(i0 + 1) * D_ + dcol] = a1;
        __syncwarp();   // PV reads done before next tile overwrites scratch
    }
}

extern "C" void kernel_launch(void* const* d_in, const int* in_sizes, int n_in,
                              void* d_out, int out_size)
{
    const float* Q  = (const float*)d_in[0];
    const float* K  = (const float*)d_in[1];
    const float* V  = (const float*)d_in[2];
    const float* E  = (const float*)d_in[3];
    const int*   uc = (const int*)d_in[4];
    float* out = (float*)d_out;

    const int nbh = out_size / (S_ * D_);   // 4096 for the bench shape
    const size_t smem = (size_t)SMEM_FLOATS * sizeof(float);  // 95904 B -> 2 CTAs/SM

    cudaFuncSetAttribute(rpsa_kernel, cudaFuncAttributeMaxDynamicSharedMemorySize, (int)smem);
    rpsa_kernel<<<nbh, NT_, smem>>>(Q, K, V, E, uc, out);
}

// round 10
// speedup vs baseline: 1.6143x; 1.0202x over previous
#include <cuda_runtime.h>
#include <math.h>

// Problem constants
constexpr int S_    = 81;    // sequence length
constexpr int D_    = 64;    // head dim
constexpr int KSTR_ = 68;    // K/E row stride: mod 8 == 4 -> conflict-free float4 row-distinct LDS
constexpr int VSTR_ = 64;    // Q/V row stride: reads are broadcast (Q) or lane-consecutive (V)
constexpr int NT_   = 512;
constexpr int NW_   = 16;
constexpr int NR_   = 4;     // query rows per tile
constexpr int NTILE_= 21;    // ceil(81/4)

constexpr int SZ_Q   = S_ * VSTR_;        // 5184
constexpr int SZ_K   = S_ * KSTR_;        // 5508
constexpr int SZ_E   = S_ * KSTR_;        // 5508 (causal slice: emb rows 80..160)
constexpr int SZ_V   = S_ * VSTR_;        // 5184
constexpr int SZ_SCR = NW_ * NR_ * S_;    // 5184 (per-warp scratch: bias M values)
constexpr int SMEM_FLOATS = SZ_Q + SZ_K + SZ_E + SZ_V + SZ_SCR; // 26568 -> 106272 B (2 CTAs/SM)

__global__ __launch_bounds__(NT_, 2)   // 2 CTAs x 512 thr: regs capped at 64, 32 warps/SM
void rpsa_kernel(const float* __restrict__ Qg_, const float* __restrict__ Kg_,
                 const float* __restrict__ Vg_, const float* __restrict__ Eg,
                 const int* __restrict__ causal_p, float* __restrict__ outg_)
{
    extern __shared__ float sm[];
    float* sQ  = sm;
    float* sK  = sQ + SZ_Q;
    float* sE  = sK + SZ_K;
    float* sV  = sE + SZ_E;
    float* sScr= sV + SZ_V;

    const int bh   = blockIdx.x;
    const int tid  = threadIdx.x;
    const int warp = tid >> 5;
    const int lane = tid & 31;
    const int causal = *causal_p;
    const float scale = 0.03608439182435161f;  // 1/sqrt(768)

    const float* Qg = Qg_ + (size_t)bh * (S_ * D_);
    const float* Kg = Kg_ + (size_t)bh * (S_ * D_);
    const float* Vg = Vg_ + (size_t)bh * (S_ * D_);
    float*     outg = outg_ + (size_t)bh * (S_ * D_);

    // ------------- Stage A: load Q, K, V, E-slice (float4, coalesced), ONE barrier ----
    #pragma unroll 1
    for (int t = tid; t < (S_ * D_) / 4; t += NT_) {
        int e = t << 2, r = e >> 6, c = e & 63;
        *(float4*)&sQ[r * VSTR_ + c] = *(const float4*)&Qg[e];
        *(float4*)&sK[r * KSTR_ + c] = *(const float4*)&Kg[e];
        *(float4*)&sV[r * VSTR_ + c] = *(const float4*)&Vg[e];
        // local E row t holds emb_table[80 + t] (rels >= 80; the only ones used when causal)
        *(float4*)&sE[r * KSTR_ + c] = *(const float4*)&Eg[(S_ - 1) * D_ + e];
    }
    __syncthreads();

    // ------------- Warp-autonomous: logits -> softmax -> PV per 4-row tile ------------
    float* scr = sScr + warp * (NR_ * S_);
    const int dcol = 2 * lane;

    for (int tile = warp; tile < NTILE_; tile += NW_) {
        const int i0   = tile * NR_;
        const int imax = min(i0 + NR_ - 1, S_ - 1);
        const int ng   = causal ? ((imax >> 5) + 1) : 3;

        int iv[NR_], ri[NR_];
        #pragma unroll
        for (int r = 0; r < NR_; r++) { iv[r] = min(i0 + r, S_ - 1); ri[r] = iv[r] * VSTR_; }
        int rowg[3];
        #pragma unroll
        for (int g = 0; g < 3; g++) rowg[g] = min(lane + 32 * g, S_ - 1) * KSTR_;

        // ---- K pass (d-outer, g-inner): accK[r][g] = Q[i_r] . K[j],  j = lane+32g ----
        float accK[NR_][3];
        #pragma unroll
        for (int r = 0; r < NR_; r++) { accK[r][0] = accK[r][1] = accK[r][2] = 0.f; }
        #pragma unroll 1
        for (int d = 0; d < D_; d += 4) {
            float4 q[NR_];
            #pragma unroll
            for (int r = 0; r < NR_; r++) q[r] = *(const float4*)&sQ[ri[r] + d];
            #pragma unroll
            for (int g = 0; g < 3; g++) {
                if (g < ng) {
                    float4 k4 = *(const float4*)&sK[rowg[g] + d];
                    #pragma unroll
                    for (int r = 0; r < NR_; r++) {
                        float a = accK[r][g];
                        a = fmaf(q[r].x, k4.x, a); a = fmaf(q[r].y, k4.y, a);
                        a = fmaf(q[r].z, k4.z, a); a = fmaf(q[r].w, k4.w, a);
                        accK[r][g] = a;
                    }
                }
            }
        }

        if (causal) {
            // ---- M pass (g-outer: only 4 accM live): accM[r] = Q[i_r].E80[t], t=lane+32g ----
            #pragma unroll
            for (int g = 0; g < 3; g++) {
                if (g < ng) {
                    float m0 = 0.f, m1 = 0.f, m2 = 0.f, m3 = 0.f;
                    const int eg = rowg[g];
                    #pragma unroll 1
                    for (int d = 0; d < D_; d += 4) {
                        float4 e4 = *(const float4*)&sE[eg + d];
                        float4 q0 = *(const float4*)&sQ[ri[0] + d];
                        float4 q1 = *(const float4*)&sQ[ri[1] + d];
                        float4 q2 = *(const float4*)&sQ[ri[2] + d];
                        float4 q3 = *(const float4*)&sQ[ri[3] + d];
                        m0 = fmaf(q0.x, e4.x, m0); m0 = fmaf(q0.y, e4.y, m0);
                        m0 = fmaf(q0.z, e4.z, m0); m0 = fmaf(q0.w, e4.w, m0);
                        m1 = fmaf(q1.x, e4.x, m1); m1 = fmaf(q1.y, e4.y, m1);
                        m1 = fmaf(q1.z, e4.z, m1); m1 = fmaf(q1.w, e4.w, m1);
                        m2 = fmaf(q2.x, e4.x, m2); m2 = fmaf(q2.y, e4.y, m2);
                        m2 = fmaf(q2.z, e4.z, m2); m2 = fmaf(q2.w, e4.w, m2);
                        m3 = fmaf(q3.x, e4.x, m3); m3 = fmaf(q3.y, e4.y, m3);
                        m3 = fmaf(q3.z, e4.z, m3); m3 = fmaf(q3.w, e4.w, m3);
                    }
                    int t = lane + 32 * g;
                    if (t < S_) {
                        scr[0 * S_ + t] = m0; scr[1 * S_ + t] = m1;
                        scr[2 * S_ + t] = m2; scr[3 * S_ + t] = m3;
                    }
                }
            }
            __syncwarp();
            // bias gather + mask into accK (accK becomes logits)
            #pragma unroll
            for (int r = 0; r < NR_; r++) {
                const int i = iv[r];
                #pragma unroll
                for (int g = 0; g < 3; g++) {
                    int j = lane + 32 * g;
                    if (g < ng && j <= i)
                        accK[r][g] = (accK[r][g] + scr[r * S_ + (i - j)]) * scale;
                    else
                        accK[r][g] = -3.0e38f;
                }
            }
            __syncwarp();   // scratch reads done before the next tile's M pass overwrites it
        } else {
            // non-causal: bias from global E rows (L2-resident), no mask
            #pragma unroll
            for (int r = 0; r < NR_; r++) {
                const int i = iv[r];
                #pragma unroll
                for (int g = 0; g < 3; g++) {
                    int j = lane + 32 * g;
                    if (j < S_) {
                        float bias = 0.f;
                        const float* erow = &Eg[(size_t)(S_ - 1 + i - j) * D_];
                        const float* qrow = &sQ[ri[r]];
                        #pragma unroll 1
                        for (int d = 0; d < D_; d += 4) {
                            float4 e4 = *(const float4*)&erow[d];
                            float4 q4 = *(const float4*)&qrow[d];
                            bias = fmaf(q4.x, e4.x, bias); bias = fmaf(q4.y, e4.y, bias);
                            bias = fmaf(q4.z, e4.z, bias); bias = fmaf(q4.w, e4.w, bias);
                        }
                        accK[r][g] = (accK[r][g] + bias) * scale;
                    } else {
                        accK[r][g] = -3.0e38f;
                    }
                }
            }
        }

        // ---- register softmax per row (lane holds j = lane, lane+32, lane+64) ----
        #pragma unroll
        for (int r = 0; r < NR_; r++) {
            float m = fmaxf(accK[r][0], fmaxf(accK[r][1], accK[r][2]));
            #pragma unroll
            for (int o = 16; o > 0; o >>= 1) m = fmaxf(m, __shfl_xor_sync(0xffffffffu, m, o));
            float e0 = expf(accK[r][0] - m);
            float e1 = expf(accK[r][1] - m);
            float e2 = expf(accK[r][2] - m);
            float s = e0 + e1 + e2;
            #pragma unroll
            for (int o = 16; o > 0; o >>= 1) s += __shfl_xor_sync(0xffffffffu, s, o);
            float inv = 1.0f / s;
            accK[r][0] = e0 * inv; accK[r][1] = e1 * inv; accK[r][2] = e2 * inv;
        }
        // masked entries are exactly 0 now; probs stay in registers.

        // ---- PV via shfl: out[i_r][dcol,dcol+1] = sum_j P[i_r][j] * V[j][:] ----
        const int jmax = causal ? imax : (S_ - 1);
        float2 a0 = {0.f, 0.f}, a1 = {0.f, 0.f}, a2 = {0.f, 0.f}, a3 = {0.f, 0.f};
        #pragma unroll
        for (int g = 0; g < 3; g++) {
            const int jhi = min(jmax, 32 * g + 31);
            #pragma unroll 1
            for (int j = 32 * g; j <= jhi; j++) {
                const int src = j - 32 * g;
                float2 v = *(const float2*)&sV[j * VSTR_ + dcol];
                float p0 = __shfl_sync(0xffffffffu, accK[0][g], src);
                float p1 = __shfl_sync(0xffffffffu, accK[1][g], src);
                float p2 = __shfl_sync(0xffffffffu, accK[2][g], src);
                float p3 = __shfl_sync(0xffffffffu, accK[3][g], src);
                a0.x = fmaf(p0, v.x, a0.x); a0.y = fmaf(p0, v.y, a0.y);
                a1.x = fmaf(p1, v.x, a1.x); a1.y = fmaf(p1, v.y, a1.y);
                a2.x = fmaf(p2, v.x, a2.x); a2.y = fmaf(p2, v.y, a2.y);
                a3.x = fmaf(p3, v.x, a3.x); a3.y = fmaf(p3, v.y, a3.y);
            }
        }
        if (i0 < S_)     *(float2*)&outg[i0 * D_ + dcol]       = a0;
        if (i0 + 1 < S_) *(float2*)&outg[(i0 + 1) * D_ + dcol] = a1;
        if (i0 + 2 < S_) *(float2*)&outg[(i0 + 2) * D_ + dcol] = a2;
        if (i0 + 3 < S_) *(float2*)&outg[(i0 + 3) * D_ + dcol] = a3;
    }
}

extern "C" void kernel_launch(void* const* d_in, const int* in_sizes, int n_in,
                              void* d_out, int out_size)
{
    const float* Q  = (const float*)d_in[0];
    const float* K  = (const float*)d_in[1];
    const float* V  = (const float*)d_in[2];
    const float* E  = (const float*)d_in[3];
    const int*   uc = (const int*)d_in[4];
    float* out = (float*)d_out;

    const int nbh = out_size / (S_ * D_);   // 4096 for the bench shape
    const size_t smem = (size_t)SMEM_FLOATS * sizeof(float);  // 106272 B -> 2 CTAs/SM

    cudaFuncSetAttribute(rpsa_kernel, cudaFuncAttributeMaxDynamicSharedMemorySize, (int)smem);
    rpsa_kernel<<<nbh, NT_, smem>>>(Q, K, V, E, uc, out);
}

// round 11
// speedup vs baseline: 1.6809x; 1.0412x over previous
#include <cuda_runtime.h>
#include <math.h>

// Problem constants
constexpr int S_    = 81;    // sequence length
constexpr int D_    = 64;    // head dim
constexpr int KSTR_ = 68;    // K/E row stride: mod 8 == 4 -> conflict-free float4 row-distinct LDS
constexpr int VSTR_ = 64;    // Q/V row stride: reads are broadcast (Q) or lane-consecutive (V)
constexpr int NT_   = 512;
constexpr int NW_   = 16;
constexpr int NR_   = 4;     // query rows per tile
constexpr int NTILE_= 21;    // ceil(81/4)

constexpr int SZ_Q   = S_ * VSTR_;        // 5184
constexpr int SZ_K   = S_ * KSTR_;        // 5508
constexpr int SZ_E   = S_ * KSTR_;        // 5508 (causal slice: emb rows 80..160)
constexpr int SZ_V   = S_ * VSTR_;        // 5184
constexpr int SCRW_  = NR_ * S_;          // 324 floats/warp = 81 float4 (M [r][t], then P [j][4])
constexpr int SZ_SCR = NW_ * SCRW_;       // 5184
constexpr int SMEM_FLOATS = SZ_Q + SZ_K + SZ_E + SZ_V + SZ_SCR; // 26568 -> 106272 B (2 CTAs/SM)

// Balanced causal schedule: tile cost ~ (1.5, 3.5, 5.5) for ng = (1, 2, 3).
// ng3 tiles (16..20) get dedicated warps; cheap ng1 tiles (0..7) are doubled/tripled.
__device__ __constant__ signed char SCHED[NW_][3] = {
    {16,-1,-1},{17,-1,-1},{18,-1,-1},{19,-1,-1},{20,-1,-1},
    { 8,-1,-1},{ 9,-1,-1},{10,-1,-1},{11,-1,-1},{12,-1,-1},{13,-1,-1},{14,-1,-1},{15,-1,-1},
    { 0, 1, 6},{ 2, 3,-1},{ 4, 5, 7}
};

__global__ __launch_bounds__(NT_, 2)   // 2 CTAs x 512 thr: regs capped at 64, 32 warps/SM
void rpsa_kernel(const float* __restrict__ Qg_, const float* __restrict__ Kg_,
                 const float* __restrict__ Vg_, const float* __restrict__ Eg,
                 const int* __restrict__ causal_p, float* __restrict__ outg_)
{
    extern __shared__ float sm[];
    float* sQ  = sm;
    float* sK  = sQ + SZ_Q;
    float* sE  = sK + SZ_K;
    float* sV  = sE + SZ_E;
    float* sScr= sV + SZ_V;

    const int bh   = blockIdx.x;
    const int tid  = threadIdx.x;
    const int warp = tid >> 5;
    const int lane = tid & 31;
    const int causal = *causal_p;
    const float scale = 0.03608439182435161f;  // 1/sqrt(768)

    const float* Qg = Qg_ + (size_t)bh * (S_ * D_);
    const float* Kg = Kg_ + (size_t)bh * (S_ * D_);
    const float* Vg = Vg_ + (size_t)bh * (S_ * D_);
    float*     outg = outg_ + (size_t)bh * (S_ * D_);

    // ------------- Stage A: load Q, K, V, E-slice (float4, coalesced), ONE barrier ----
    #pragma unroll 1
    for (int t = tid; t < (S_ * D_) / 4; t += NT_) {
        int e = t << 2, r = e >> 6, c = e & 63;
        *(float4*)&sQ[r * VSTR_ + c] = *(const float4*)&Qg[e];
        *(float4*)&sK[r * KSTR_ + c] = *(const float4*)&Kg[e];
        *(float4*)&sV[r * VSTR_ + c] = *(const float4*)&Vg[e];
        // local E row t holds emb_table[80 + t] (rels >= 80; the only ones used when causal)
        *(float4*)&sE[r * KSTR_ + c] = *(const float4*)&Eg[(S_ - 1) * D_ + e];
    }
    __syncthreads();

    // ------------- Per-warp tile list: balanced schedule (causal) or interleaved ------
    int myTiles[3]; int nMine = 0;
    if (causal) {
        #pragma unroll
        for (int s = 0; s < 3; s++) {
            int t = SCHED[warp][s];
            if (t >= 0) myTiles[nMine++] = t;
        }
    } else {
        for (int t = warp; t < NTILE_; t += NW_) myTiles[nMine++] = t;
    }

    float* scr = sScr + warp * SCRW_;
    float4* scr4 = (float4*)scr;
    const int dcol = 2 * lane;

    #pragma unroll 1
    for (int m = 0; m < nMine; m++) {
        const int tile = myTiles[m];
        const int i0   = tile * NR_;
        const int imax = min(i0 + NR_ - 1, S_ - 1);
        const int ng   = causal ? ((imax >> 5) + 1) : 3;

        int iv[NR_], ri[NR_];
        #pragma unroll
        for (int r = 0; r < NR_; r++) { iv[r] = min(i0 + r, S_ - 1); ri[r] = iv[r] * VSTR_; }
        int rowg[3];
        #pragma unroll
        for (int g = 0; g < 3; g++) rowg[g] = min(lane + 32 * g, S_ - 1) * KSTR_;

        // ---- K pass (d-outer, g-inner): accK[r][g] = Q[i_r] . K[j],  j = lane+32g ----
        float accK[NR_][3];
        #pragma unroll
        for (int r = 0; r < NR_; r++) { accK[r][0] = accK[r][1] = accK[r][2] = 0.f; }
        #pragma unroll 1
        for (int d = 0; d < D_; d += 4) {
            float4 q[NR_];
            #pragma unroll
            for (int r = 0; r < NR_; r++) q[r] = *(const float4*)&sQ[ri[r] + d];
            #pragma unroll
            for (int g = 0; g < 3; g++) {
                if (g < ng) {
                    float4 k4 = *(const float4*)&sK[rowg[g] + d];
                    #pragma unroll
                    for (int r = 0; r < NR_; r++) {
                        float a = accK[r][g];
                        a = fmaf(q[r].x, k4.x, a); a = fmaf(q[r].y, k4.y, a);
                        a = fmaf(q[r].z, k4.z, a); a = fmaf(q[r].w, k4.w, a);
                        accK[r][g] = a;
                    }
                }
            }
        }

        if (causal) {
            // ---- M pass (g-outer, only 4 acc live): accM[r] = Q[i_r].E80[t], t=lane+32g ----
            #pragma unroll
            for (int g = 0; g < 3; g++) {
                if (g < ng) {
                    float m0 = 0.f, m1 = 0.f, m2 = 0.f, m3 = 0.f;
                    const int eg = rowg[g];
                    #pragma unroll 1
                    for (int d = 0; d < D_; d += 4) {
                        float4 e4 = *(const float4*)&sE[eg + d];
                        float4 q0 = *(const float4*)&sQ[ri[0] + d];
                        float4 q1 = *(const float4*)&sQ[ri[1] + d];
                        float4 q2 = *(const float4*)&sQ[ri[2] + d];
                        float4 q3 = *(const float4*)&sQ[ri[3] + d];
                        m0 = fmaf(q0.x, e4.x, m0); m0 = fmaf(q0.y, e4.y, m0);
                        m0 = fmaf(q0.z, e4.z, m0); m0 = fmaf(q0.w, e4.w, m0);
                        m1 = fmaf(q1.x, e4.x, m1); m1 = fmaf(q1.y, e4.y, m1);
                        m1 = fmaf(q1.z, e4.z, m1); m1 = fmaf(q1.w, e4.w, m1);
                        m2 = fmaf(q2.x, e4.x, m2); m2 = fmaf(q2.y, e4.y, m2);
                        m2 = fmaf(q2.z, e4.z, m2); m2 = fmaf(q2.w, e4.w, m2);
                        m3 = fmaf(q3.x, e4.x, m3); m3 = fmaf(q3.y, e4.y, m3);
                        m3 = fmaf(q3.z, e4.z, m3); m3 = fmaf(q3.w, e4.w, m3);
                    }
                    int t = lane + 32 * g;
                    if (t < S_) {
                        scr[0 * S_ + t] = m0; scr[1 * S_ + t] = m1;
                        scr[2 * S_ + t] = m2; scr[3 * S_ + t] = m3;
                    }
                }
            }
            __syncwarp();
            // bias gather + mask into accK (accK becomes logits)
            #pragma unroll
            for (int r = 0; r < NR_; r++) {
                const int i = iv[r];
                #pragma unroll
                for (int g = 0; g < 3; g++) {
                    int j = lane + 32 * g;
                    if (g < ng && j <= i)
                        accK[r][g] = (accK[r][g] + scr[r * S_ + (i - j)]) * scale;
                    else
                        accK[r][g] = -3.0e38f;
                }
            }
            __syncwarp();   // M reads done before P store overwrites the scratch
        } else {
            // non-causal: bias from global E rows (L2-resident), no mask
            #pragma unroll
            for (int r = 0; r < NR_; r++) {
                const int i = iv[r];
                #pragma unroll
                for (int g = 0; g < 3; g++) {
                    int j = lane + 32 * g;
                    if (j < S_) {
                        float bias = 0.f;
                        const float* erow = &Eg[(size_t)(S_ - 1 + i - j) * D_];
                        const float* qrow = &sQ[ri[r]];
                        #pragma unroll 1
                        for (int d = 0; d < D_; d += 4) {
                            float4 e4 = *(const float4*)&erow[d];
                            float4 q4 = *(const float4*)&qrow[d];
                            bias = fmaf(q4.x, e4.x, bias); bias = fmaf(q4.y, e4.y, bias);
                            bias = fmaf(q4.z, e4.z, bias); bias = fmaf(q4.w, e4.w, bias);
                        }
                        accK[r][g] = (accK[r][g] + bias) * scale;
                    } else {
                        accK[r][g] = -3.0e38f;
                    }
                }
            }
        }

        // ---- register softmax per row (lane holds j = lane, lane+32, lane+64) ----
        #pragma unroll
        for (int r = 0; r < NR_; r++) {
            float mx = fmaxf(accK[r][0], fmaxf(accK[r][1], accK[r][2]));
            #pragma unroll
            for (int o = 16; o > 0; o >>= 1) mx = fmaxf(mx, __shfl_xor_sync(0xffffffffu, mx, o));
            float e0 = expf(accK[r][0] - mx);
            float e1 = expf(accK[r][1] - mx);
            float e2 = expf(accK[r][2] - mx);
            float s = e0 + e1 + e2;
            #pragma unroll
            for (int o = 16; o > 0; o >>= 1) s += __shfl_xor_sync(0xffffffffu, s, o);
            float inv = 1.0f / s;
            accK[r][0] = e0 * inv; accK[r][1] = e1 * inv; accK[r][2] = e2 * inv;
        }

        // ---- P -> scratch as [j][4] float4 (one STS.128 per group, consecutive) ----
        #pragma unroll
        for (int g = 0; g < 3; g++) {
            int j = lane + 32 * g;
            if (j < S_)
                scr4[j] = make_float4(accK[0][g], accK[1][g], accK[2][g], accK[3][g]);
        }
        __syncwarp();

        // ---- PV: per j, ONE broadcast float4 (probs of 4 rows) + float2 V ----
        const int jmax = causal ? imax : (S_ - 1);
        float2 a0 = {0.f, 0.f}, a1 = {0.f, 0.f}, a2 = {0.f, 0.f}, a3 = {0.f, 0.f};
        #pragma unroll 2
        for (int j = 0; j <= jmax; j++) {
            float4 p  = scr4[j];                              // broadcast: 1 wavefront
            float2 v  = *(const float2*)&sV[j * VSTR_ + dcol];
            a0.x = fmaf(p.x, v.x, a0.x); a0.y = fmaf(p.x, v.y, a0.y);
            a1.x = fmaf(p.y, v.x, a1.x); a1.y = fmaf(p.y, v.y, a1.y);
            a2.x = fmaf(p.z, v.x, a2.x); a2.y = fmaf(p.z, v.y, a2.y);
            a3.x = fmaf(p.w, v.x, a3.x); a3.y = fmaf(p.w, v.y, a3.y);
        }
        if (i0 < S_)     *(float2*)&outg[i0 * D_ + dcol]       = a0;
        if (i0 + 1 < S_) *(float2*)&outg[(i0 + 1) * D_ + dcol] = a1;
        if (i0 + 2 < S_) *(float2*)&outg[(i0 + 2) * D_ + dcol] = a2;
        if (i0 + 3 < S_) *(float2*)&outg[(i0 + 3) * D_ + dcol] = a3;
        __syncwarp();   // PV reads done before next tile's M pass overwrites scratch
    }
}

extern "C" void kernel_launch(void* const* d_in, const int* in_sizes, int n_in,
                              void* d_out, int out_size)
{
    const float* Q  = (const float*)d_in[0];
    const float* K  = (const float*)d_in[1];
    const float* V  = (const float*)d_in[2];
    const float* E  = (const float*)d_in[3];
    const int*   uc = (const int*)d_in[4];
    float* out = (float*)d_out;

    const int nbh = out_size / (S_ * D_);   // 4096 for the bench shape
    const size_t smem = (size_t)SMEM_FLOATS * sizeof(float);  // 106272 B -> 2 CTAs/SM

    cudaFuncSetAttribute(rpsa_kernel, cudaFuncAttributeMaxDynamicSharedMemorySize, (int)smem);
    rpsa_kernel<<<nbh, NT_, smem>>>(Q, K, V, E, uc, out);
}

// round 12
// speedup vs baseline: 1.6996x; 1.0111x over previous
#include <cuda_runtime.h>
#include <math.h>

typedef unsigned long long u64;

// packed fp32x2 FMA: one issue, two fp32 FMAs (sm_100+; ptxas never auto-fuses this)
__device__ __forceinline__ void fma2(u64& acc, u64 a, u64 b) {
    asm("fma.rn.f32x2 %0, %1, %2, %0;" : "+l"(acc) : "l"(a), "l"(b));
}
__device__ __forceinline__ float hsum2(u64 v) {
    float lo, hi;
    asm("mov.b64 {%0, %1}, %2;" : "=f"(lo), "=f"(hi) : "l"(v));
    return lo + hi;
}

// Problem constants
constexpr int S_    = 81;    // sequence length
constexpr int D_    = 64;    // head dim
constexpr int KSTR_ = 68;    // K/E row stride (floats): 272B rows -> 16B-aligned, conflict-free LDS.128
constexpr int VSTR_ = 64;    // Q/V row stride
constexpr int NT_   = 512;
constexpr int NW_   = 16;
constexpr int NR_   = 4;     // query rows per tile
constexpr int NTILE_= 21;    // ceil(81/4)

constexpr int SZ_Q   = S_ * VSTR_;        // 5184
constexpr int SZ_K   = S_ * KSTR_;        // 5508
constexpr int SZ_E   = S_ * KSTR_;        // 5508 (causal slice: emb rows 80..160)
constexpr int SZ_V   = S_ * VSTR_;        // 5184
constexpr int SCRW_  = NR_ * S_;          // 324 floats/warp (M [r][t], then P [j][4])
constexpr int SZ_SCR = NW_ * SCRW_;       // 5184
constexpr int SMEM_FLOATS = SZ_Q + SZ_K + SZ_E + SZ_V + SZ_SCR; // 26568 -> 106272 B (2 CTAs/SM)

// Balanced causal schedule: tile cost ~ (1.5, 3.5, 5.5) for ng = (1, 2, 3).
__device__ __constant__ signed char SCHED[NW_][3] = {
    {16,-1,-1},{17,-1,-1},{18,-1,-1},{19,-1,-1},{20,-1,-1},
    { 8,-1,-1},{ 9,-1,-1},{10,-1,-1},{11,-1,-1},{12,-1,-1},{13,-1,-1},{14,-1,-1},{15,-1,-1},
    { 0, 1, 6},{ 2, 3,-1},{ 4, 5, 7}
};

__global__ __launch_bounds__(NT_, 2)   // 2 CTAs x 512 thr: regs capped at 64, 32 warps/SM
void rpsa_kernel(const float* __restrict__ Qg_, const float* __restrict__ Kg_,
                 const float* __restrict__ Vg_, const float* __restrict__ Eg,
                 const int* __restrict__ causal_p, float* __restrict__ outg_)
{
    extern __shared__ float sm[];
    float* sQ  = sm;
    float* sK  = sQ + SZ_Q;
    float* sE  = sK + SZ_K;
    float* sV  = sE + SZ_E;
    float* sScr= sV + SZ_V;

    const int bh   = blockIdx.x;
    const int tid  = threadIdx.x;
    const int warp = tid >> 5;
    const int lane = tid & 31;
    const int causal = *causal_p;
    const float scale = 0.03608439182435161f;  // 1/sqrt(768)

    const float* Qg = Qg_ + (size_t)bh * (S_ * D_);
    const float* Kg = Kg_ + (size_t)bh * (S_ * D_);
    const float* Vg = Vg_ + (size_t)bh * (S_ * D_);
    float*     outg = outg_ + (size_t)bh * (S_ * D_);

    // ------------- Stage A: load Q, K, V, E-slice (float4, coalesced), ONE barrier ----
    #pragma unroll 1
    for (int t = tid; t < (S_ * D_) / 4; t += NT_) {
        int e = t << 2, r = e >> 6, c = e & 63;
        *(float4*)&sQ[r * VSTR_ + c] = *(const float4*)&Qg[e];
        *(float4*)&sK[r * KSTR_ + c] = *(const float4*)&Kg[e];
        *(float4*)&sV[r * VSTR_ + c] = *(const float4*)&Vg[e];
        // local E row t holds emb_table[80 + t] (rels >= 80; only ones used when causal)
        *(float4*)&sE[r * KSTR_ + c] = *(const float4*)&Eg[(S_ - 1) * D_ + e];
    }
    __syncthreads();

    // ------------- Per-warp tile list: balanced (causal) or interleaved ---------------
    int myTiles[3]; int nMine = 0;
    if (causal) {
        #pragma unroll
        for (int s = 0; s < 3; s++) {
            int t = SCHED[warp][s];
            if (t >= 0) myTiles[nMine++] = t;
        }
    } else {
        for (int t = warp; t < NTILE_; t += NW_) myTiles[nMine++] = t;
    }

    float* scr = sScr + warp * SCRW_;
    float4* scr4 = (float4*)scr;
    const int dcol = 2 * lane;

    #pragma unroll 1
    for (int m = 0; m < nMine; m++) {
        const int tile = myTiles[m];
        const int i0   = tile * NR_;
        const int imax = min(i0 + NR_ - 1, S_ - 1);
        const int ng   = causal ? ((imax >> 5) + 1) : 3;

        int iv[NR_], ri[NR_];
        #pragma unroll
        for (int r = 0; r < NR_; r++) { iv[r] = min(i0 + r, S_ - 1); ri[r] = iv[r] * VSTR_; }
        int rowg[3];
        #pragma unroll
        for (int g = 0; g < 3; g++) rowg[g] = min(lane + 32 * g, S_ - 1) * KSTR_;

        // ---- K pass (f32x2): accK[r][g] = Q[i_r] . K[j],  j = lane+32g ----
        u64 accK2[NR_][3];
        #pragma unroll
        for (int r = 0; r < NR_; r++) { accK2[r][0] = 0ull; accK2[r][1] = 0ull; accK2[r][2] = 0ull; }
        #pragma unroll 1
        for (int d = 0; d < D_; d += 4) {
            ulonglong2 q2[NR_];
            #pragma unroll
            for (int r = 0; r < NR_; r++) q2[r] = *(const ulonglong2*)&sQ[ri[r] + d];
            #pragma unroll
            for (int g = 0; g < 3; g++) {
                if (g < ng) {
                    ulonglong2 k2 = *(const ulonglong2*)&sK[rowg[g] + d];
                    #pragma unroll
                    for (int r = 0; r < NR_; r++) {
                        fma2(accK2[r][g], q2[r].x, k2.x);
                        fma2(accK2[r][g], q2[r].y, k2.y);
                    }
                }
            }
        }
        float accK[NR_][3];
        #pragma unroll
        for (int r = 0; r < NR_; r++)
            #pragma unroll
            for (int g = 0; g < 3; g++)
                accK[r][g] = hsum2(accK2[r][g]);

        if (causal) {
            // ---- M pass (f32x2, g-outer): accM[r] = Q[i_r] . E80[t],  t = lane+32g ----
            #pragma unroll
            for (int g = 0; g < 3; g++) {
                if (g < ng) {
                    u64 m2[NR_] = {0ull, 0ull, 0ull, 0ull};
                    const int eg = rowg[g];
                    #pragma unroll 1
                    for (int d = 0; d < D_; d += 4) {
                        ulonglong2 e2 = *(const ulonglong2*)&sE[eg + d];
                        #pragma unroll
                        for (int r = 0; r < NR_; r++) {
                            ulonglong2 q2 = *(const ulonglong2*)&sQ[ri[r] + d];
                            fma2(m2[r], q2.x, e2.x);
                            fma2(m2[r], q2.y, e2.y);
                        }
                    }
                    int t = lane + 32 * g;
                    if (t < S_) {
                        #pragma unroll
                        for (int r = 0; r < NR_; r++) scr[r * S_ + t] = hsum2(m2[r]);
                    }
                }
            }
            __syncwarp();
            // bias gather + mask into accK (accK becomes logits)
            #pragma unroll
            for (int r = 0; r < NR_; r++) {
                const int i = iv[r];
                #pragma unroll
                for (int g = 0; g < 3; g++) {
                    int j = lane + 32 * g;
                    if (g < ng && j <= i)
                        accK[r][g] = (accK[r][g] + scr[r * S_ + (i - j)]) * scale;
                    else
                        accK[r][g] = -3.0e38f;
                }
            }
            __syncwarp();   // M reads done before P store overwrites the scratch
        } else {
            // non-causal: bias from global E rows (L2-resident), f32x2, no mask
            #pragma unroll
            for (int r = 0; r < NR_; r++) {
                const int i = iv[r];
                #pragma unroll
                for (int g = 0; g < 3; g++) {
                    int j = lane + 32 * g;
                    if (j < S_) {
                        u64 b2 = 0ull;
                        const float* erow = &Eg[(size_t)(S_ - 1 + i - j) * D_];
                        const float* qrow = &sQ[ri[r]];
                        #pragma unroll 1
                        for (int d = 0; d < D_; d += 4) {
                            ulonglong2 e2 = *(const ulonglong2*)&erow[d];
                            ulonglong2 q2 = *(const ulonglong2*)&qrow[d];
                            fma2(b2, q2.x, e2.x);
                            fma2(b2, q2.y, e2.y);
                        }
                        accK[r][g] = (accK[r][g] + hsum2(b2)) * scale;
                    } else {
                        accK[r][g] = -3.0e38f;
                    }
                }
            }
        }

        // ---- register softmax per row (lane holds j = lane, lane+32, lane+64) ----
        #pragma unroll
        for (int r = 0; r < NR_; r++) {
            float mx = fmaxf(accK[r][0], fmaxf(accK[r][1], accK[r][2]));
            #pragma unroll
            for (int o = 16; o > 0; o >>= 1) mx = fmaxf(mx, __shfl_xor_sync(0xffffffffu, mx, o));
            float e0 = expf(accK[r][0] - mx);
            float e1 = expf(accK[r][1] - mx);
            float e2 = expf(accK[r][2] - mx);
            float s = e0 + e1 + e2;
            #pragma unroll
            for (int o = 16; o > 0; o >>= 1) s += __shfl_xor_sync(0xffffffffu, s, o);
            float inv = 1.0f / s;
            accK[r][0] = e0 * inv; accK[r][1] = e1 * inv; accK[r][2] = e2 * inv;
        }

        // ---- P -> scratch as [j][4] float4 (one STS.128 per group, consecutive) ----
        #pragma unroll
        for (int g = 0; g < 3; g++) {
            int j = lane + 32 * g;
            if (j < S_)
                scr4[j] = make_float4(accK[0][g], accK[1][g], accK[2][g], accK[3][g]);
        }
        __syncwarp();

        // ---- PV: per j, ONE broadcast float4 (probs of 4 rows) + float2 V ----
        const int jmax = causal ? imax : (S_ - 1);
        float2 a0 = {0.f, 0.f}, a1 = {0.f, 0.f}, a2 = {0.f, 0.f}, a3 = {0.f, 0.f};
        #pragma unroll 2
        for (int j = 0; j <= jmax; j++) {
            float4 p  = scr4[j];                              // broadcast: 1 wavefront
            float2 v  = *(const float2*)&sV[j * VSTR_ + dcol];
            a0.x = fmaf(p.x, v.x, a0.x); a0.y = fmaf(p.x, v.y, a0.y);
            a1.x = fmaf(p.y, v.x, a1.x); a1.y = fmaf(p.y, v.y, a1.y);
            a2.x = fmaf(p.z, v.x, a2.x); a2.y = fmaf(p.z, v.y, a2.y);
            a3.x = fmaf(p.w, v.x, a3.x); a3.y = fmaf(p.w, v.y, a3.y);
        }
        if (i0 < S_)     *(float2*)&outg[i0 * D_ + dcol]       = a0;
        if (i0 + 1 < S_) *(float2*)&outg[(i0 + 1) * D_ + dcol] = a1;
        if (i0 + 2 < S_) *(float2*)&outg[(i0 + 2) * D_ + dcol] = a2;
        if (i0 + 3 < S_) *(float2*)&outg[(i0 + 3) * D_ + dcol] = a3;
        __syncwarp();   // PV reads done before next tile's M pass overwrites scratch
    }
}

extern "C" void kernel_launch(void* const* d_in, const int* in_sizes, int n_in,
                              void* d_out, int out_size)
{
    const float* Q  = (const float*)d_in[0];
    const float* K  = (const float*)d_in[1];
    const float* V  = (const float*)d_in[2];
    const float* E  = (const float*)d_in[3];
    const int*   uc = (const int*)d_in[4];
    float* out = (float*)d_out;

    const int nbh = out_size / (S_ * D_);   // 4096 for the bench shape
    const size_t smem = (size_t)SMEM_FLOATS * sizeof(float);  // 106272 B -> 2 CTAs/SM

    cudaFuncSetAttribute(rpsa_kernel, cudaFuncAttributeMaxDynamicSharedMemorySize, (int)smem);
    rpsa_kernel<<<nbh, NT_, smem>>>(Q, K, V, E, uc, out);
}

// round 13
// speedup vs baseline: 1.7641x; 1.0379x over previous
#include <cuda_runtime.h>
#include <math.h>

typedef unsigned long long u64;

// packed fp32x2 FMA: one issue, two fp32 FMAs (sm_100+; ptxas never auto-fuses this)
__device__ __forceinline__ void fma2(u64& acc, u64 a, u64 b) {
    asm("fma.rn.f32x2 %0, %1, %2, %0;" : "+l"(acc) : "l"(a), "l"(b));
}
__device__ __forceinline__ float hsum2(u64 v) {
    float lo, hi;
    asm("mov.b64 {%0, %1}, %2;" : "=f"(lo), "=f"(hi) : "l"(v));
    return lo + hi;
}

// Problem constants
constexpr int S_    = 81;    // sequence length
constexpr int D_    = 64;    // head dim
constexpr int KSTR_ = 68;    // K/E row stride (floats): 272B rows -> 16B-aligned, conflict-free LDS.128
constexpr int VSTR_ = 64;    // Q/V row stride
constexpr int NT_   = 512;
constexpr int NW_   = 16;
constexpr int NR_   = 4;     // query rows per tile
constexpr int NTILE_= 21;    // ceil(81/4)

constexpr int SZ_Q   = S_ * VSTR_;        // 5184
constexpr int SZ_K   = S_ * KSTR_;        // 5508
constexpr int SZ_E   = S_ * KSTR_;        // 5508 (causal slice: emb rows 80..160)
constexpr int SZ_V   = S_ * VSTR_;        // 5184
constexpr int SCRW_  = NR_ * S_;          // 324 floats/warp (M [r][t], then P [j][4])
constexpr int SZ_SCR = NW_ * SCRW_;       // 5184
constexpr int SMEM_FLOATS = SZ_Q + SZ_K + SZ_E + SZ_V + SZ_SCR; // 26568 -> 106272 B (2 CTAs/SM)

// Balanced causal schedule: tile cost ~ (1.5, 3.5, 5.5) for ng = (1, 2, 3).
__device__ __constant__ signed char SCHED[NW_][3] = {
    {16,-1,-1},{17,-1,-1},{18,-1,-1},{19,-1,-1},{20,-1,-1},
    { 8,-1,-1},{ 9,-1,-1},{10,-1,-1},{11,-1,-1},{12,-1,-1},{13,-1,-1},{14,-1,-1},{15,-1,-1},
    { 0, 1, 6},{ 2, 3,-1},{ 4, 5, 7}
};

__global__ __launch_bounds__(NT_, 2)   // 2 CTAs x 512 thr: regs capped at 64, 32 warps/SM
void rpsa_kernel(const float* __restrict__ Qg_, const float* __restrict__ Kg_,
                 const float* __restrict__ Vg_, const float* __restrict__ Eg,
                 const int* __restrict__ causal_p, float* __restrict__ outg_)
{
    extern __shared__ float sm[];
    float* sQ  = sm;
    float* sK  = sQ + SZ_Q;
    float* sE  = sK + SZ_K;
    float* sV  = sE + SZ_E;
    float* sScr= sV + SZ_V;

    const int bh   = blockIdx.x;
    const int tid  = threadIdx.x;
    const int warp = tid >> 5;
    const int lane = tid & 31;
    const int causal = *causal_p;
    const float scale = 0.03608439182435161f;  // 1/sqrt(768)

    const float* Qg = Qg_ + (size_t)bh * (S_ * D_);
    const float* Kg = Kg_ + (size_t)bh * (S_ * D_);
    const float* Vg = Vg_ + (size_t)bh * (S_ * D_);
    float*     outg = outg_ + (size_t)bh * (S_ * D_);

    // ------------- Stage A: load Q, K, V, E-slice (float4, coalesced), ONE barrier ----
    #pragma unroll 1
    for (int t = tid; t < (S_ * D_) / 4; t += NT_) {
        int e = t << 2, r = e >> 6, c = e & 63;
        *(float4*)&sQ[r * VSTR_ + c] = *(const float4*)&Qg[e];
        *(float4*)&sK[r * KSTR_ + c] = *(const float4*)&Kg[e];
        *(float4*)&sV[r * VSTR_ + c] = *(const float4*)&Vg[e];
        // local E row t holds emb_table[80 + t] (rels >= 80; only ones used when causal)
        *(float4*)&sE[r * KSTR_ + c] = *(const float4*)&Eg[(S_ - 1) * D_ + e];
    }
    __syncthreads();

    // ------------- Per-warp tile list: balanced (causal) or interleaved ---------------
    int myTiles[3]; int nMine = 0;
    if (causal) {
        #pragma unroll
        for (int s = 0; s < 3; s++) {
            int t = SCHED[warp][s];
            if (t >= 0) myTiles[nMine++] = t;
        }
    } else {
        for (int t = warp; t < NTILE_; t += NW_) myTiles[nMine++] = t;
    }

    float* scr = sScr + warp * SCRW_;
    float4* scr4 = (float4*)scr;
    const int dcol = 2 * lane;

    #pragma unroll 1
    for (int m = 0; m < nMine; m++) {
        const int tile = myTiles[m];
        const int i0   = tile * NR_;
        const int imax = min(i0 + NR_ - 1, S_ - 1);
        const int ng   = causal ? ((imax >> 5) + 1) : 3;

        int iv[NR_], ri[NR_];
        #pragma unroll
        for (int r = 0; r < NR_; r++) { iv[r] = min(i0 + r, S_ - 1); ri[r] = iv[r] * VSTR_; }
        int rowg[3];
        #pragma unroll
        for (int g = 0; g < 3; g++) rowg[g] = min(lane + 32 * g, S_ - 1) * KSTR_;

        // ---- K pass (f32x2, unroll 4 -> LDS immediate offsets): accK[r][g] = Q.K ----
        u64 accK2[NR_][3];
        #pragma unroll
        for (int r = 0; r < NR_; r++) { accK2[r][0] = 0ull; accK2[r][1] = 0ull; accK2[r][2] = 0ull; }
        #pragma unroll 4
        for (int d = 0; d < D_; d += 4) {
            ulonglong2 q2[NR_];
            #pragma unroll
            for (int r = 0; r < NR_; r++) q2[r] = *(const ulonglong2*)&sQ[ri[r] + d];
            #pragma unroll
            for (int g = 0; g < 3; g++) {
                if (g < ng) {
                    ulonglong2 k2 = *(const ulonglong2*)&sK[rowg[g] + d];
                    #pragma unroll
                    for (int r = 0; r < NR_; r++) {
                        fma2(accK2[r][g], q2[r].x, k2.x);
                        fma2(accK2[r][g], q2[r].y, k2.y);
                    }
                }
            }
        }
        float accK[NR_][3];
        #pragma unroll
        for (int r = 0; r < NR_; r++)
            #pragma unroll
            for (int g = 0; g < 3; g++)
                accK[r][g] = hsum2(accK2[r][g]);

        if (causal) {
            // ---- M pass (f32x2, g-outer, unroll 4): accM[r] = Q[i_r] . E80[t] ----
            #pragma unroll
            for (int g = 0; g < 3; g++) {
                if (g < ng) {
                    u64 m2[NR_] = {0ull, 0ull, 0ull, 0ull};
                    const int eg = rowg[g];
                    #pragma unroll 4
                    for (int d = 0; d < D_; d += 4) {
                        ulonglong2 e2 = *(const ulonglong2*)&sE[eg + d];
                        #pragma unroll
                        for (int r = 0; r < NR_; r++) {
                            ulonglong2 q2 = *(const ulonglong2*)&sQ[ri[r] + d];
                            fma2(m2[r], q2.x, e2.x);
                            fma2(m2[r], q2.y, e2.y);
                        }
                    }
                    int t = lane + 32 * g;
                    if (t < S_) {
                        #pragma unroll
                        for (int r = 0; r < NR_; r++) scr[r * S_ + t] = hsum2(m2[r]);
                    }
                }
            }
            __syncwarp();
            // bias gather + mask into accK (accK becomes logits)
            #pragma unroll
            for (int r = 0; r < NR_; r++) {
                const int i = iv[r];
                #pragma unroll
                for (int g = 0; g < 3; g++) {
                    int j = lane + 32 * g;
                    if (g < ng && j <= i)
                        accK[r][g] = (accK[r][g] + scr[r * S_ + (i - j)]) * scale;
                    else
                        accK[r][g] = -3.0e38f;
                }
            }
            __syncwarp();   // M reads done before P store overwrites the scratch
        } else {
            // non-causal: bias from global E rows (L2-resident), f32x2, no mask
            #pragma unroll
            for (int r = 0; r < NR_; r++) {
                const int i = iv[r];
                #pragma unroll
                for (int g = 0; g < 3; g++) {
                    int j = lane + 32 * g;
                    if (j < S_) {
                        u64 b2 = 0ull;
                        const float* erow = &Eg[(size_t)(S_ - 1 + i - j) * D_];
                        const float* qrow = &sQ[ri[r]];
                        #pragma unroll 4
                        for (int d = 0; d < D_; d += 4) {
                            ulonglong2 e2 = *(const ulonglong2*)&erow[d];
                            ulonglong2 q2 = *(const ulonglong2*)&qrow[d];
                            fma2(b2, q2.x, e2.x);
                            fma2(b2, q2.y, e2.y);
                        }
                        accK[r][g] = (accK[r][g] + hsum2(b2)) * scale;
                    } else {
                        accK[r][g] = -3.0e38f;
                    }
                }
            }
        }

        // ---- register softmax per row (lane holds j = lane, lane+32, lane+64) ----
        #pragma unroll
        for (int r = 0; r < NR_; r++) {
            float mx = fmaxf(accK[r][0], fmaxf(accK[r][1], accK[r][2]));
            #pragma unroll
            for (int o = 16; o > 0; o >>= 1) mx = fmaxf(mx, __shfl_xor_sync(0xffffffffu, mx, o));
            float e0 = expf(accK[r][0] - mx);
            float e1 = expf(accK[r][1] - mx);
            float e2 = expf(accK[r][2] - mx);
            float s = e0 + e1 + e2;
            #pragma unroll
            for (int o = 16; o > 0; o >>= 1) s += __shfl_xor_sync(0xffffffffu, s, o);
            float inv = 1.0f / s;
            accK[r][0] = e0 * inv; accK[r][1] = e1 * inv; accK[r][2] = e2 * inv;
        }

        // ---- P -> scratch as [j][4] float4 (one STS.128 per group, consecutive) ----
        #pragma unroll
        for (int g = 0; g < 3; g++) {
            int j = lane + 32 * g;
            if (j < S_)
                scr4[j] = make_float4(accK[0][g], accK[1][g], accK[2][g], accK[3][g]);
        }
        __syncwarp();

        // ---- PV: per j, ONE broadcast float4 (probs of 4 rows) + float2 V ----
        const int jmax = causal ? imax : (S_ - 1);
        float2 a0 = {0.f, 0.f}, a1 = {0.f, 0.f}, a2 = {0.f, 0.f}, a3 = {0.f, 0.f};
        #pragma unroll 4
        for (int j = 0; j <= jmax; j++) {
            float4 p  = scr4[j];                              // broadcast: 1 wavefront
            float2 v  = *(const float2*)&sV[j * VSTR_ + dcol];
            a0.x = fmaf(p.x, v.x, a0.x); a0.y = fmaf(p.x, v.y, a0.y);
            a1.x = fmaf(p.y, v.x, a1.x); a1.y = fmaf(p.y, v.y, a1.y);
            a2.x = fmaf(p.z, v.x, a2.x); a2.y = fmaf(p.z, v.y, a2.y);
            a3.x = fmaf(p.w, v.x, a3.x); a3.y = fmaf(p.w, v.y, a3.y);
        }
        if (i0 < S_)     *(float2*)&outg[i0 * D_ + dcol]       = a0;
        if (i0 + 1 < S_) *(float2*)&outg[(i0 + 1) * D_ + dcol] = a1;
        if (i0 + 2 < S_) *(float2*)&outg[(i0 + 2) * D_ + dcol] = a2;
        if (i0 + 3 < S_) *(float2*)&outg[(i0 + 3) * D_ + dcol] = a3;
        __syncwarp();   // PV reads done before next tile's M pass overwrites scratch
    }
}

extern "C" void kernel_launch(void* const* d_in, const int* in_sizes, int n_in,
                              void* d_out, int out_size)
{
    const float* Q  = (const float*)d_in[0];
    const float* K  = (const float*)d_in[1];
    const float* V  = (const float*)d_in[2];
    const float* E  = (const float*)d_in[3];
    const int*   uc = (const int*)d_in[4];
    float* out = (float*)d_out;

    const int nbh = out_size / (S_ * D_);   // 4096 for the bench shape
    const size_t smem = (size_t)SMEM_FLOATS * sizeof(float);  // 106272 B -> 2 CTAs/SM

    cudaFuncSetAttribute(rpsa_kernel, cudaFuncAttributeMaxDynamicSharedMemorySize, (int)smem);
    rpsa_kernel<<<nbh, NT_, smem>>>(Q, K, V, E, uc, out);
}

// round 17
// speedup vs baseline: 2.5986x; 1.4731x over previous
#include <cuda_runtime.h>
#include <cuda_bf16.h>
#include <math.h>
#include <cstdint>
#include <cstddef>

typedef unsigned long long u64;

// ---------------------------------------------------------------- constants
constexpr int S_  = 81;
constexpr int D_  = 64;
constexpr int NT_ = 384;
constexpr int NW_ = 12;
constexpr int NTILE_ = 21;          // epilogue: 4 query rows per tile
constexpr int LSTR_ = 85;           // sLog/sM row stride (floats)

// smem layout (bytes), causal path
constexpr int OFF_AH  = 0;          // Q hi bf16: 96 rows x 128B (81..95 zero)
constexpr int OFF_AL  = 12288;      // Q lo
constexpr int OFF_BH  = 24576;      // B hi: 176 rows x 128B; rows 0..80=K, 88..168=E80+t, rest 0
constexpr int OFF_BL  = 47104;
constexpr int OFF_V   = 69632;      // V fp32 81x64
constexpr int OFF_SCR = 90368;      // 12 warps x 81 float4
constexpr int SMEM_TOTAL = 105920;  // x2 CTAs = 211840 B -> 2 CTAs/SM
// post-MMA aliases: sLog @ 0 (81x85 f32 = 27540 B), sM @ 28160 (27540 B, ends 55700 < OFF_V)

__device__ __constant__ signed char SCHED12[NW_][2] = {
    {9,-1},{10,8},{11,7},
    {20,-1},{19,-1},{18,0},{17,1},{16,2},{15,3},{14,4},{13,5},{12,6}
};

// ---------------------------------------------------------------- helpers
__device__ __forceinline__ uint32_t smem_u32_of(const void* p) {
    uint32_t a;
    asm("{ .reg .u64 t; cvta.to.shared.u64 t, %1; cvt.u32.u64 %0, t; }" : "=r"(a) : "l"(p));
    return a;
}
__device__ __forceinline__ uint32_t sw128(uint32_t off) { return off ^ ((off >> 3) & 0x70); }

__device__ __forceinline__ void ldmatrix_x4(uint32_t* r, uint32_t addr) {
    asm volatile("ldmatrix.sync.aligned.m8n8.x4.shared.b16 {%0,%1,%2,%3}, [%4];"
                 : "=r"(r[0]), "=r"(r[1]), "=r"(r[2]), "=r"(r[3]) : "r"(addr));
}
// B operand for mma.row.col with K-major ([n][k]) storage: NON-trans ldmatrix.
__device__ __forceinline__ void ldmatrix_x2(uint32_t* r, uint32_t addr) {
    asm volatile("ldmatrix.sync.aligned.m8n8.x2.shared.b16 {%0,%1}, [%2];"
                 : "=r"(r[0]), "=r"(r[1]) : "r"(addr));
}
__device__ __forceinline__ void mma_bf16(float* c, const uint32_t* a, const uint32_t* b) {
    asm volatile("mma.sync.aligned.m16n8k16.row.col.f32.bf16.bf16.f32 "
                 "{%0,%1,%2,%3}, {%4,%5,%6,%7}, {%8,%9}, {%0,%1,%2,%3};"
                 : "+f"(c[0]), "+f"(c[1]), "+f"(c[2]), "+f"(c[3])
                 : "r"(a[0]), "r"(a[1]), "r"(a[2]), "r"(a[3]), "r"(b[0]), "r"(b[1]));
}
__device__ __forceinline__ void store_split(char* ph, char* pl, float2 v) {
    __nv_bfloat16 h0 = __float2bfloat16(v.x);
    __nv_bfloat16 h1 = __float2bfloat16(v.y);
    __nv_bfloat16 l0 = __float2bfloat16(v.x - __bfloat162float(h0));
    __nv_bfloat16 l1 = __float2bfloat16(v.y - __bfloat162float(h1));
    *(__nv_bfloat162*)ph = __halves2bfloat162(h0, h1);
    *(__nv_bfloat162*)pl = __halves2bfloat162(l0, l1);
}

// ---------------------------------------------------------------- kernel
__global__ __launch_bounds__(NT_, 2)
void rpsa_kernel(const float* __restrict__ Qg_, const float* __restrict__ Kg_,
                 const float* __restrict__ Vg_, const float* __restrict__ Eg,
                 const int* __restrict__ causal_p, float* __restrict__ outg_)
{
    extern __shared__ char sb[];
    const uint32_t smem_u32 = smem_u32_of(sb);
    const int bh   = blockIdx.x;
    const int tid  = threadIdx.x;
    const int warp = tid >> 5;
    const int lane = tid & 31;
    const int causal = *causal_p;
    const float scale = 0.03608439182435161f;   // 1/sqrt(768)

    const float* Qg = Qg_ + (size_t)bh * (S_ * D_);
    const float* Kg = Kg_ + (size_t)bh * (S_ * D_);
    const float* Vg = Vg_ + (size_t)bh * (S_ * D_);
    float*     outg = outg_ + (size_t)bh * (S_ * D_);

    if (causal) {
        // ============== fused logits GEMM via mma.sync (bf16 3-split) ==============
        // ---- stage: zero pads; split Q->A, K->B[0..80], E80+t->B[88+t]; V fp32 ----
        for (int t = tid; t < 240; t += NT_) {            // A rows 81..95 zero
            int off = 81 * 128 + t * 8;
            *(u64*)(sb + OFF_AH + off) = 0ull; *(u64*)(sb + OFF_AL + off) = 0ull;
        }
        for (int t = tid; t < 224; t += NT_) {            // B rows 81..87 & 169..175 zero
            int off = (t < 112) ? (81 * 128 + t * 8) : (169 * 128 + (t - 112) * 8);
            *(u64*)(sb + OFF_BH + off) = 0ull; *(u64*)(sb + OFF_BL + off) = 0ull;
        }
        for (int t = tid; t < S_ * 32; t += NT_) {        // 81 rows x 32 col-pairs
            int row = t >> 5, cp = (t & 31) * 2;
            uint32_t sw = sw128((uint32_t)(row * 128 + cp * 2));
            float2 q = *(const float2*)&Qg[row * D_ + cp];
            store_split(sb + OFF_AH + sw, sb + OFF_AL + sw, q);
            float2 k = *(const float2*)&Kg[row * D_ + cp];
            store_split(sb + OFF_BH + sw, sb + OFF_BL + sw, k);
            uint32_t swE = sw128((uint32_t)((88 + row) * 128 + cp * 2));
            float2 e = *(const float2*)&Eg[(size_t)(80 + row) * D_ + cp];
            store_split(sb + OFF_BH + swE, sb + OFF_BL + swE, e);
        }
        float* sV = (float*)(sb + OFF_V);
        for (int t = tid; t < S_ * 16; t += NT_) {
            int row = t >> 4, c4 = (t & 15) * 4;
            *(float4*)&sV[row * D_ + c4] = *(const float4*)&Vg[row * D_ + c4];
        }
        __syncthreads();

        // ---- warp (strip s, part): K-part tiles n=0..; E-part tiles n=11.. ----
        const int s    = warp >> 1;              // 0..5, rows 16s..16s+15
        const int part = warp & 1;               // 0 = K logits, 1 = E bias
        const int m0   = 16 * s;
        const int imax = min(m0 + 15, S_ - 1);
        const int ntiles = imax / 8 + 1;         // <= 11
        const int ntBase = part ? 11 : 0;        // E tiles start at n-tile 11 (col 88)

        float C[11][4];
        #pragma unroll
        for (int t = 0; t < 11; t++) { C[t][0] = C[t][1] = C[t][2] = C[t][3] = 0.f; }

        const int arow = m0 + (lane & 15);
        const int acolq = (lane >> 4) << 3;             // 0 or 8
        const int brow_l = lane & 7;
        const int bcol_l = (lane & 8) ? 8 : 0;

        #pragma unroll
        for (int kc = 0; kc < 4; kc++) {
            const int k0 = kc * 16;
            uint32_t aoff = sw128((uint32_t)(arow * 128 + (k0 + acolq) * 2));
            uint32_t ah[4], al[4];
            ldmatrix_x4(ah, smem_u32 + OFF_AH + aoff);
            ldmatrix_x4(al, smem_u32 + OFF_AL + aoff);
            #pragma unroll
            for (int t = 0; t < 11; t++) {
                if (t < ntiles) {
                    int n0 = (ntBase + t) * 8;
                    uint32_t boff = sw128((uint32_t)((n0 + brow_l) * 128 + (k0 + bcol_l) * 2));
                    uint32_t bhf[2], blf[2];
                    ldmatrix_x2(bhf, smem_u32 + OFF_BH + boff);
                    ldmatrix_x2(blf, smem_u32 + OFF_BL + boff);
                    mma_bf16(C[t], ah, bhf);
                    mma_bf16(C[t], ah, blf);
                    mma_bf16(C[t], al, bhf);
                }
            }
        }
        __syncthreads();   // all A/B smem reads done -> safe to alias with sLog/sM

        // ---- store C fragments: K tiles -> sLog[i][j], E tiles -> sM[i][t] ----
        float* sLog = (float*)sb;
        float* sM   = (float*)(sb + 28160);
        {
            const int trow = lane >> 2, tc = (lane & 3) * 2;
            #pragma unroll
            for (int t = 0; t < 11; t++) {
                if (t < ntiles) {
                    int n0 = (ntBase + t) * 8;
                    #pragma unroll
                    for (int h = 0; h < 2; h++) {
                        int row = m0 + trow + 8 * h;
                        if (row <= S_ - 1) {
                            int col = n0 + tc;
                            float c0 = C[t][2 * h], c1 = C[t][2 * h + 1];
                            if (part == 0) {
                                if (col     <= S_ - 1) sLog[row * LSTR_ + col]     = c0;
                                if (col + 1 <= S_ - 1) sLog[row * LSTR_ + col + 1] = c1;
                            } else {
                                int te = col - 88;
                                if (te     <= S_ - 1) sM[row * LSTR_ + te]     = c0;
                                if (te + 1 <= S_ - 1) sM[row * LSTR_ + te + 1] = c1;
                            }
                        }
                    }
                }
            }
        }
        __syncthreads();

        // ---- epilogue: gather+mask -> register softmax -> PV ----
        float* scrW = (float*)(sb + OFF_SCR) + warp * (4 * S_);
        float4* scr4 = (float4*)scrW;
        const int dcol = 2 * lane;

        #pragma unroll 1
        for (int sc = 0; sc < 2; sc++) {
            const int tile = SCHED12[warp][sc];
            if (tile < 0) break;
            const int i0   = tile * 4;
            const int tmax = min(i0 + 3, S_ - 1);
            const int ng   = (tmax >> 5) + 1;

            int iv[4];
            #pragma unroll
            for (int r = 0; r < 4; r++) iv[r] = min(i0 + r, S_ - 1);

            float P[4][3];
            #pragma unroll
            for (int r = 0; r < 4; r++) {
                const int i = iv[r];
                #pragma unroll
                for (int g = 0; g < 3; g++) {
                    int j = lane + 32 * g;
                    if (g < ng && j <= i)
                        P[r][g] = (sLog[i * LSTR_ + j] + sM[i * LSTR_ + (i - j)]) * scale;
                    else
                        P[r][g] = -3.0e38f;
                }
            }
            #pragma unroll
            for (int r = 0; r < 4; r++) {
                float mx = fmaxf(P[r][0], fmaxf(P[r][1], P[r][2]));
                #pragma unroll
                for (int o = 16; o > 0; o >>= 1) mx = fmaxf(mx, __shfl_xor_sync(0xffffffffu, mx, o));
                float e0 = expf(P[r][0] - mx), e1 = expf(P[r][1] - mx), e2 = expf(P[r][2] - mx);
                float ssum = e0 + e1 + e2;
                #pragma unroll
                for (int o = 16; o > 0; o >>= 1) ssum += __shfl_xor_sync(0xffffffffu, ssum, o);
                float inv = 1.0f / ssum;
                P[r][0] = e0 * inv; P[r][1] = e1 * inv; P[r][2] = e2 * inv;
            }
            #pragma unroll
            for (int g = 0; g < 3; g++) {
                int j = lane + 32 * g;
                if (j < S_) scr4[j] = make_float4(P[0][g], P[1][g], P[2][g], P[3][g]);
            }
            __syncwarp();
            float2 a0 = {0.f,0.f}, a1 = {0.f,0.f}, a2 = {0.f,0.f}, a3 = {0.f,0.f};
            #pragma unroll 4
            for (int j = 0; j <= tmax; j++) {
                float4 p = scr4[j];
                float2 v = *(const float2*)&sV[j * D_ + dcol];
                a0.x = fmaf(p.x, v.x, a0.x); a0.y = fmaf(p.x, v.y, a0.y);
                a1.x = fmaf(p.y, v.x, a1.x); a1.y = fmaf(p.y, v.y, a1.y);
                a2.x = fmaf(p.z, v.x, a2.x); a2.y = fmaf(p.z, v.y, a2.y);
                a3.x = fmaf(p.w, v.x, a3.x); a3.y = fmaf(p.w, v.y, a3.y);
            }
            if (i0 < S_)     *(float2*)&outg[i0 * D_ + dcol]       = a0;
            if (i0 + 1 < S_) *(float2*)&outg[(i0 + 1) * D_ + dcol] = a1;
            if (i0 + 2 < S_) *(float2*)&outg[(i0 + 2) * D_ + dcol] = a2;
            if (i0 + 3 < S_) *(float2*)&outg[(i0 + 3) * D_ + dcol] = a3;
            __syncwarp();
        }
    } else {
        // ======================= non-causal SIMT fallback =======================
        float* sQn = (float*)sb;
        float* sKn = sQn + S_ * D_;
        float* sVn = sKn + S_ * 68;
        float* scrn = sVn + S_ * D_;
        for (int t = tid; t < (S_ * D_) / 4; t += NT_) {
            int e = t << 2, r = e >> 6, c = e & 63;
            *(float4*)&sQn[r * D_ + c] = *(const float4*)&Qg[e];
            *(float4*)&sKn[r * 68 + c] = *(const float4*)&Kg[e];
            *(float4*)&sVn[r * D_ + c] = *(const float4*)&Vg[e];
        }
        __syncthreads();
        float* scrW = scrn + warp * (4 * S_);
        float4* scr4 = (float4*)scrW;
        const int dcol = 2 * lane;
        for (int tile = warp; tile < NTILE_; tile += NW_) {
            const int i0 = tile * 4;
            int iv[4], ri[4];
            #pragma unroll
            for (int r = 0; r < 4; r++) { iv[r] = min(i0 + r, S_ - 1); ri[r] = iv[r] * D_; }
            int ki[3];
            #pragma unroll
            for (int g = 0; g < 3; g++) ki[g] = min(lane + 32 * g, S_ - 1) * 68;

            float acc[4][3];
            #pragma unroll
            for (int r = 0; r < 4; r++) { acc[r][0] = acc[r][1] = acc[r][2] = 0.f; }
            #pragma unroll 4
            for (int d = 0; d < D_; d += 4) {
                float4 q[4];
                #pragma unroll
                for (int r = 0; r < 4; r++) q[r] = *(const float4*)&sQn[ri[r] + d];
                #pragma unroll
                for (int g = 0; g < 3; g++) {
                    float4 k4 = *(const float4*)&sKn[ki[g] + d];
                    #pragma unroll
                    for (int r = 0; r < 4; r++) {
                        float a = acc[r][g];
                        a = fmaf(q[r].x, k4.x, a); a = fmaf(q[r].y, k4.y, a);
                        a = fmaf(q[r].z, k4.z, a); a = fmaf(q[r].w, k4.w, a);
                        acc[r][g] = a;
                    }
                }
            }
            #pragma unroll
            for (int r = 0; r < 4; r++) {
                const int i = iv[r];
                #pragma unroll
                for (int g = 0; g < 3; g++) {
                    int j = lane + 32 * g;
                    if (j < S_) {
                        float b = 0.f;
                        const float* er = &Eg[(size_t)(S_ - 1 + i - j) * D_];
                        const float* qr = &sQn[ri[r]];
                        #pragma unroll 4
                        for (int d = 0; d < D_; d += 4) {
                            float4 e4 = *(const float4*)&er[d];
                            float4 q4 = *(const float4*)&qr[d];
                            b = fmaf(q4.x, e4.x, b); b = fmaf(q4.y, e4.y, b);
                            b = fmaf(q4.z, e4.z, b); b = fmaf(q4.w, e4.w, b);
                        }
                        acc[r][g] = (acc[r][g] + b) * scale;
                    } else acc[r][g] = -3.0e38f;
                }
            }
            #pragma unroll
            for (int r = 0; r < 4; r++) {
                float mx = fmaxf(acc[r][0], fmaxf(acc[r][1], acc[r][2]));
                #pragma unroll
                for (int o = 16; o > 0; o >>= 1) mx = fmaxf(mx, __shfl_xor_sync(0xffffffffu, mx, o));
                float e0 = expf(acc[r][0] - mx), e1 = expf(acc[r][1] - mx), e2 = expf(acc[r][2] - mx);
                float ssum = e0 + e1 + e2;
                #pragma unroll
                for (int o = 16; o > 0; o >>= 1) ssum += __shfl_xor_sync(0xffffffffu, ssum, o);
                float inv = 1.0f / ssum;
                acc[r][0] = e0 * inv; acc[r][1] = e1 * inv; acc[r][2] = e2 * inv;
            }
            #pragma unroll
            for (int g = 0; g < 3; g++) {
                int j = lane + 32 * g;
                if (j < S_) scr4[j] = make_float4(acc[0][g], acc[1][g], acc[2][g], acc[3][g]);
            }
            __syncwarp();
            float2 a0 = {0.f,0.f}, a1 = {0.f,0.f}, a2 = {0.f,0.f}, a3 = {0.f,0.f};
            #pragma unroll 4
            for (int j = 0; j < S_; j++) {
                float4 p = scr4[j];
                float2 v = *(const float2*)&sVn[j * D_ + dcol];
                a0.x = fmaf(p.x, v.x, a0.x); a0.y = fmaf(p.x, v.y, a0.y);
                a1.x = fmaf(p.y, v.x, a1.x); a1.y = fmaf(p.y, v.y, a1.y);
                a2.x = fmaf(p.z, v.x, a2.x); a2.y = fmaf(p.z, v.y, a2.y);
                a3.x = fmaf(p.w, v.x, a3.x); a3.y = fmaf(p.w, v.y, a3.y);
            }
            if (i0 < S_)     *(float2*)&outg[i0 * D_ + dcol]       = a0;
            if (i0 + 1 < S_) *(float2*)&outg[(i0 + 1) * D_ + dcol] = a1;
            if (i0 + 2 < S_) *(float2*)&outg[(i0 + 2) * D_ + dcol] = a2;
            if (i0 + 3 < S_) *(float2*)&outg[(i0 + 3) * D_ + dcol] = a3;
            __syncwarp();
        }
    }
}

extern "C" void kernel_launch(void* const* d_in, const int* in_sizes, int n_in,
                              void* d_out, int out_size)
{
    const float* Q  = (const float*)d_in[0];
    const float* K  = (const float*)d_in[1];
    const float* V  = (const float*)d_in[2];
    const float* E  = (const float*)d_in[3];
    const int*   uc = (const int*)d_in[4];
    float* out = (float*)d_out;

    const int nbh = out_size / (S_ * D_);   // 4096 for the bench shape

    cudaFuncSetAttribute(rpsa_kernel, cudaFuncAttributeMaxDynamicSharedMemorySize, SMEM_TOTAL);
    rpsa_kernel<<<nbh, NT_, SMEM_TOTAL>>>(Q, K, V, E, uc, out);
}